// round 1
// baseline (speedup 1.0000x reference)
#include <cuda_runtime.h>
#include <math.h>

#define VV 16000
#define BB 8
#define TT 1024
#define DD 64
#define FF 256
#define EE 8
#define BT (BB*TT)

// ---------------- device scratch (no allocations allowed) ----------------
__device__ float g_emb[BT*DD];        // 2 MB   embedded tokens
__device__ float g_A[BT*DD];          // 2 MB   x_t @ Wm + bm
__device__ float g_mem[BT*DD];        // 2 MB   recurrent state per step
__device__ float g_out[BT*DD];        // 2 MB   post-LN activations
__device__ float g_eo[BT*EE*DD];      // 16.8 MB per-expert FFN outputs (pre-gate)

typedef unsigned long long ull;

__device__ __forceinline__ ull pack2(float lo, float hi){
    ull r; asm("mov.b64 %0, {%1, %2};" : "=l"(r) : "f"(lo), "f"(hi)); return r;
}
__device__ __forceinline__ void unpack2(ull v, float& lo, float& hi){
    asm("mov.b64 {%0, %1}, %2;" : "=f"(lo), "=f"(hi) : "l"(v));
}
__device__ __forceinline__ void fma2(ull& d, ull a, ull b){
    asm("fma.rn.f32x2 %0, %1, %2, %0;" : "+l"(d) : "l"(a), "l"(b));
}
__device__ __forceinline__ float tanh_fast(float x){
    float r; asm("tanh.approx.f32 %0, %1;" : "=f"(r) : "f"(x)); return r;
}

// ---------------- K1: embedding gather + A = emb @ Wm + bm ----------------
__global__ void k_embA(const int* __restrict__ x, const float* __restrict__ tab,
                       const float* __restrict__ Wm, const float* __restrict__ bm)
{
    int bt = blockIdx.x;
    int d  = threadIdx.x;
    __shared__ __align__(16) float xs[DD];
    float v = tab[x[bt]*DD + d];
    xs[d] = v;
    g_emb[bt*DD + d] = v;
    __syncthreads();
    float acc = bm[d];
    const float4* xr = (const float4*)xs;
#pragma unroll
    for (int k4 = 0; k4 < 16; k4++){
        float4 m4 = xr[k4];
        acc += m4.x*Wm[(k4*4+0)*DD+d] + m4.y*Wm[(k4*4+1)*DD+d]
             + m4.z*Wm[(k4*4+2)*DD+d] + m4.w*Wm[(k4*4+3)*DD+d];
    }
    g_A[bt*DD + d] = acc;
}

// ---------------- K2: recurrence (blocks 0..7) || expert FFN (blocks 8..) ----------------
__global__ __launch_bounds__(256, 2) void k_main(
    const float* __restrict__ Um,
    const float* __restrict__ W1, const float* __restrict__ b1,
    const float* __restrict__ W2, const float* __restrict__ b2)
{
    if (blockIdx.x < BB) {
        // -------- sequential recurrence for batch b, mem stored per step --------
        __shared__ __align__(16) float sm_mem[DD];
        __shared__ float sp[4][DD];
        int b   = blockIdx.x;
        int tid = threadIdx.x;
        int d = tid & 63, q = tid >> 6;       // 4-way split of the k-reduction
        float um[16];
#pragma unroll
        for (int j = 0; j < 16; j++) um[j] = Um[(q*16 + j)*DD + d];
        if (q == 0) sm_mem[d] = 0.f;
        __syncthreads();
        const float* Ab = g_A  + b*TT*DD;
        float*       Mb = g_mem + b*TT*DD;
        float a_next = (q == 0) ? Ab[d] : 0.f;   // prefetched A for step t
        for (int t = 0; t < TT; t++){
            float a_pref = 0.f;
            if (q == 0 && t + 1 < TT) a_pref = Ab[(t+1)*DD + d];  // hide L2 latency
            float p = 0.f;
            const float4* mv = (const float4*)(sm_mem + q*16);
#pragma unroll
            for (int j4 = 0; j4 < 4; j4++){
                float4 m4 = mv[j4];
                p += m4.x*um[j4*4+0] + m4.y*um[j4*4+1] + m4.z*um[j4*4+2] + m4.w*um[j4*4+3];
            }
            sp[q][d] = p;
            __syncthreads();
            if (q == 0){
                float v = a_next + sp[0][d] + sp[1][d] + sp[2][d] + sp[3][d];
                float m = tanh_fast(v);
                sm_mem[d]   = m;
                Mb[t*DD + d] = m;
            }
            a_next = a_pref;
            __syncthreads();
        }
    } else {
        // -------- dense 8-expert FFN for 16 tokens, gate-independent --------
        __shared__ __align__(16) float Xs[16][68];
        __shared__ float Hs[16][260];
        int tid  = threadIdx.x;
        int tok0 = (blockIdx.x - BB) * 16;
        for (int i = tid; i < 16*DD; i += 256){
            int tk = i >> 6, k = i & 63;
            Xs[tk][k] = g_emb[(tok0 + tk)*DD + k];
        }
        __syncthreads();
        for (int e = 0; e < EE; e++){
            { // phase A: H = gelu(X @ W1[e] + b1[e]); thread owns one f column
                int f = tid;
                const float* W1e = W1 + (e*DD)*FF + f;
                float w1c[DD];
#pragma unroll
                for (int k = 0; k < DD; k++) w1c[k] = W1e[k*FF];
                float hb = b1[e*FF + f];
#pragma unroll 2
                for (int tk = 0; tk < 16; tk++){
                    float a = hb;
                    const float4* xr = (const float4*)(&Xs[tk][0]);
#pragma unroll
                    for (int k4 = 0; k4 < 16; k4++){
                        float4 xv = xr[k4];
                        a += xv.x*w1c[k4*4+0] + xv.y*w1c[k4*4+1]
                           + xv.z*w1c[k4*4+2] + xv.w*w1c[k4*4+3];
                    }
                    // exact-erf GELU (matches approximate=False)
                    float h = 0.5f * a * (1.0f + erff(a * 0.70710678118654752440f));
                    Hs[tk][f] = h;
                }
            }
            __syncthreads();
            { // phase B: eo = H @ W2[e] + b2[e]; thread owns (d, 4 tokens)
                int d = tid & 63, tg = tid >> 6;
                const float* W2e = W2 + (e*FF)*DD + d;
                float bb = b2[e*DD + d];
                float acc0 = bb, acc1 = bb, acc2 = bb, acc3 = bb;
                int t0 = tg*4;
#pragma unroll 4
                for (int f = 0; f < FF; f++){
                    float w = W2e[f*DD];
                    acc0 += Hs[t0+0][f]*w;
                    acc1 += Hs[t0+1][f]*w;
                    acc2 += Hs[t0+2][f]*w;
                    acc3 += Hs[t0+3][f]*w;
                }
                int base = ((tok0 + t0)*EE + e)*DD + d;
                g_eo[base + 0*EE*DD] = acc0;
                g_eo[base + 1*EE*DD] = acc1;
                g_eo[base + 2*EE*DD] = acc2;
                g_eo[base + 3*EE*DD] = acc3;
            }
            __syncthreads();
        }
    }
}

// ---------------- K3: gates (from stored mem) + gated sum + residual + LN ----------------
__global__ __launch_bounds__(256) void k_combine(
    const float* __restrict__ Wg, const float* __restrict__ bg,
    const float* __restrict__ ln_g, const float* __restrict__ ln_b)
{
    __shared__ float sWg[DD*EE];
    __shared__ float sg[DD], sb[DD], sbg[EE];
    int tid = threadIdx.x;
    for (int i = tid; i < DD*EE; i += 256) sWg[i] = Wg[i];
    if (tid < DD){ sg[tid] = ln_g[tid]; sb[tid] = ln_b[tid]; }
    if (tid < EE) sbg[tid] = bg[tid];
    __syncthreads();

    int bt = blockIdx.x*256 + tid;     // one token per thread (8192 exactly)
    float gl[EE];
#pragma unroll
    for (int e = 0; e < EE; e++) gl[e] = sbg[e];
    const float4* mr = (const float4*)(g_mem + bt*DD);
#pragma unroll
    for (int k4 = 0; k4 < 16; k4++){
        float4 m4 = mr[k4];
#pragma unroll
        for (int e = 0; e < EE; e++)
            gl[e] += m4.x*sWg[(k4*4+0)*EE+e] + m4.y*sWg[(k4*4+1)*EE+e]
                   + m4.z*sWg[(k4*4+2)*EE+e] + m4.w*sWg[(k4*4+3)*EE+e];
    }
    float mx = gl[0];
#pragma unroll
    for (int e = 1; e < EE; e++) mx = fmaxf(mx, gl[e]);
    float s = 0.f;
#pragma unroll
    for (int e = 0; e < EE; e++){ gl[e] = expf(gl[e]-mx); s += gl[e]; }
    float inv = 1.f/s;
#pragma unroll
    for (int e = 0; e < EE; e++) gl[e] *= inv;

    float acc[DD];
    const float4* er = (const float4*)(g_emb + bt*DD);
#pragma unroll
    for (int i = 0; i < 16; i++){
        float4 v = er[i];
        acc[4*i] = v.x; acc[4*i+1] = v.y; acc[4*i+2] = v.z; acc[4*i+3] = v.w;
    }
#pragma unroll
    for (int e = 0; e < EE; e++){
        float g = gl[e];
        const float4* eor = (const float4*)(g_eo + (bt*EE + e)*DD);
#pragma unroll
        for (int i = 0; i < 16; i++){
            float4 v = eor[i];
            acc[4*i]   += g*v.x; acc[4*i+1] += g*v.y;
            acc[4*i+2] += g*v.z; acc[4*i+3] += g*v.w;
        }
    }
    float mu = 0.f;
#pragma unroll
    for (int i = 0; i < DD; i++) mu += acc[i];
    mu *= (1.f/DD);
    float var = 0.f;
#pragma unroll
    for (int i = 0; i < DD; i++){ float c = acc[i]-mu; var += c*c; }
    var *= (1.f/DD);
    float rs = rsqrtf(var + 1e-5f);
    float4* orow = (float4*)(g_out + bt*DD);
#pragma unroll
    for (int i = 0; i < 16; i++){
        float4 o;
        o.x = sg[4*i+0]*(acc[4*i+0]-mu)*rs + sb[4*i+0];
        o.y = sg[4*i+1]*(acc[4*i+1]-mu)*rs + sb[4*i+1];
        o.z = sg[4*i+2]*(acc[4*i+2]-mu)*rs + sb[4*i+2];
        o.w = sg[4*i+3]*(acc[4*i+3]-mu)*rs + sb[4*i+3];
        orow[i] = o;
    }
}

// ---------------- K4: head GEMM  logits = out @ head_W + head_b  (f32x2 FFMA2) ----------------
// Block tile 128x128, K=64 fully resident; per-thread 8 rows x 8 cols,
// accumulators are row-pairs packed in f32x2 (A stored transposed so a row-pair = one LDS.64).
#define HEAD_SMEM ((64*130 + 64*128)*4)

__global__ __launch_bounds__(256, 2) void k_head(
    const float* __restrict__ hW, const float* __restrict__ hb, float* __restrict__ out)
{
    extern __shared__ float smf[];
    float* As = smf;              // [64][130]  A^T: As[k*130 + row]
    float* Ws = smf + 64*130;     // [64][128]  Ws[k*128 + col]
    int tid = threadIdx.x;
    int n0 = blockIdx.x * 128;
    int m0 = blockIdx.y * 128;

    for (int i = tid; i < 2048; i += 256){          // A tile: 128 rows x 64 k, transposed
        int row = i >> 4, k4 = i & 15;
        float4 v = *(const float4*)(g_out + (m0+row)*DD + k4*4);
        As[(k4*4+0)*130 + row] = v.x;
        As[(k4*4+1)*130 + row] = v.y;
        As[(k4*4+2)*130 + row] = v.z;
        As[(k4*4+3)*130 + row] = v.w;
    }
    for (int i = tid; i < 2048; i += 256){          // W tile: 64 k x 128 cols
        int k = i >> 5, c4 = i & 31;
        float4 v = *(const float4*)(hW + (size_t)k*VV + n0 + c4*4);
        *(float4*)(Ws + k*128 + c4*4) = v;
    }
    __syncthreads();

    int tx = tid & 15, ty = tid >> 4;
    int r0 = ty*8, cb = tx*2;                       // cols: cb+32j, cb+32j+1 (conflict-free)
    ull acc[4][8];
#pragma unroll
    for (int j = 0; j < 4; j++){
        float b0  = hb[n0 + cb + 32*j];
        float b1v = hb[n0 + cb + 32*j + 1];
        ull p0 = pack2(b0,b0), p1 = pack2(b1v,b1v);
#pragma unroll
        for (int i = 0; i < 4; i++){ acc[i][2*j] = p0; acc[i][2*j+1] = p1; }
    }
#pragma unroll 4
    for (int k = 0; k < 64; k++){
        const float* Ak = As + k*130 + r0;
        ull a0 = *(const ull*)(Ak + 0);
        ull a1 = *(const ull*)(Ak + 2);
        ull a2 = *(const ull*)(Ak + 4);
        ull a3 = *(const ull*)(Ak + 6);
        const float* Wk = Ws + k*128 + cb;
#pragma unroll
        for (int j = 0; j < 4; j++){
            ull wp = *(const ull*)(Wk + 32*j);
            float w0, w1; unpack2(wp, w0, w1);
            ull wd0 = pack2(w0,w0), wd1 = pack2(w1,w1);
            fma2(acc[0][2*j],   a0, wd0);
            fma2(acc[1][2*j],   a1, wd0);
            fma2(acc[2][2*j],   a2, wd0);
            fma2(acc[3][2*j],   a3, wd0);
            fma2(acc[0][2*j+1], a0, wd1);
            fma2(acc[1][2*j+1], a1, wd1);
            fma2(acc[2][2*j+1], a2, wd1);
            fma2(acc[3][2*j+1], a3, wd1);
        }
    }
#pragma unroll
    for (int i = 0; i < 4; i++){
        size_t rlo = (size_t)(m0 + r0 + 2*i) * VV;
#pragma unroll
        for (int j = 0; j < 4; j++){
            float lo0, hi0, lo1, hi1;
            unpack2(acc[i][2*j],   lo0, hi0);
            unpack2(acc[i][2*j+1], lo1, hi1);
            int c = n0 + cb + 32*j;
            *(float2*)(out + rlo + c)      = make_float2(lo0, lo1);  // row m0+r0+2i
            *(float2*)(out + rlo + VV + c) = make_float2(hi0, hi1);  // row m0+r0+2i+1
        }
    }
}

// ---------------- launch ----------------
extern "C" void kernel_launch(void* const* d_in, const int* in_sizes, int n_in,
                              void* d_out, int out_size)
{
    const int*   x     = (const int*)  d_in[0];
    const float* tab   = (const float*)d_in[1];
    const float* Wm    = (const float*)d_in[2];
    const float* Um    = (const float*)d_in[3];
    const float* bm    = (const float*)d_in[4];
    const float* Wg    = (const float*)d_in[5];
    const float* bg    = (const float*)d_in[6];
    const float* W1    = (const float*)d_in[7];
    const float* b1    = (const float*)d_in[8];
    const float* W2    = (const float*)d_in[9];
    const float* b2    = (const float*)d_in[10];
    const float* ln_g  = (const float*)d_in[11];
    const float* ln_b  = (const float*)d_in[12];
    const float* headW = (const float*)d_in[13];
    const float* headb = (const float*)d_in[14];
    float* out = (float*)d_out;

    k_embA<<<BT, DD>>>(x, tab, Wm, bm);
    k_main<<<BB + BT/16, 256>>>(Um, W1, b1, W2, b2);           // recurrence || FFN
    k_combine<<<BT/256, 256>>>(Wg, bg, ln_g, ln_b);
    cudaFuncSetAttribute(k_head, cudaFuncAttributeMaxDynamicSharedMemorySize, HEAD_SMEM);
    k_head<<<dim3(VV/128, BT/128), 256, HEAD_SMEM>>>(headW, headb, out);
}

// round 6
// speedup vs baseline: 1.0019x; 1.0019x over previous
#include <cuda_runtime.h>
#include <cuda_bf16.h>
#include <cstdint>
#include <stdint.h>
#include <math.h>

#define VV 16000
#define BB 8
#define TT 1024
#define DD 64
#define FF 256
#define EE 8
#define BT (BB*TT)

// ---------------- device scratch (no allocations allowed) ----------------
__device__ float g_emb[BT*DD];        // 2 MB   embedded tokens
__device__ float g_A[BT*DD];          // 2 MB   x_t @ Wm + bm
__device__ float g_mem[BT*DD];        // 2 MB   recurrent state per step
__device__ float g_out[BT*DD];        // 2 MB   post-LN activations
__device__ float g_eo[BT*EE*DD];      // 16.8 MB per-expert FFN outputs (pre-gate)

typedef unsigned long long ull;

__device__ __forceinline__ float tanh_fast(float x){
    float r; asm("tanh.approx.f32 %0, %1;" : "=f"(r) : "f"(x)); return r;
}
// pack two f32 -> one b32 bf16x2: lo -> low 16 bits, hi -> high 16 bits
__device__ __forceinline__ unsigned bf2(float lo, float hi){
    unsigned r; asm("cvt.rn.bf16x2.f32 %0, %1, %2;" : "=r"(r) : "f"(hi), "f"(lo)); return r;
}
__device__ __forceinline__ uint32_t smem_u32(const void* p){
    uint32_t a; asm("{ .reg .u64 t; cvta.to.shared.u64 t, %1; cvt.u32.u64 %0, t; }" : "=r"(a) : "l"(p));
    return a;
}

// ---------------- K1: embedding gather + A = emb @ Wm + bm ----------------
__global__ void k_embA(const int* __restrict__ x, const float* __restrict__ tab,
                       const float* __restrict__ Wm, const float* __restrict__ bm)
{
    int bt = blockIdx.x;
    int d  = threadIdx.x;
    __shared__ __align__(16) float xs[DD];
    float v = tab[x[bt]*DD + d];
    xs[d] = v;
    g_emb[bt*DD + d] = v;
    __syncthreads();
    float acc = bm[d];
    const float4* xr = (const float4*)xs;
#pragma unroll
    for (int k4 = 0; k4 < 16; k4++){
        float4 m4 = xr[k4];
        acc += m4.x*Wm[(k4*4+0)*DD+d] + m4.y*Wm[(k4*4+1)*DD+d]
             + m4.z*Wm[(k4*4+2)*DD+d] + m4.w*Wm[(k4*4+3)*DD+d];
    }
    g_A[bt*DD + d] = acc;
}

// ---------------- K2: recurrence (blocks 0..7) || expert FFN (blocks 8..) ----------------
__global__ __launch_bounds__(256, 2) void k_main(
    const float* __restrict__ Um,
    const float* __restrict__ W1, const float* __restrict__ b1,
    const float* __restrict__ W2, const float* __restrict__ b2)
{
    if (blockIdx.x < BB) {
        __shared__ __align__(16) float sm_mem[DD];
        __shared__ float sp[4][DD];
        int b   = blockIdx.x;
        int tid = threadIdx.x;
        int d = tid & 63, q = tid >> 6;
        float um[16];
#pragma unroll
        for (int j = 0; j < 16; j++) um[j] = Um[(q*16 + j)*DD + d];
        if (q == 0) sm_mem[d] = 0.f;
        __syncthreads();
        const float* Ab = g_A  + b*TT*DD;
        float*       Mb = g_mem + b*TT*DD;
        float a_next = (q == 0) ? Ab[d] : 0.f;
        for (int t = 0; t < TT; t++){
            float a_pref = 0.f;
            if (q == 0 && t + 1 < TT) a_pref = Ab[(t+1)*DD + d];
            float p = 0.f;
            const float4* mv = (const float4*)(sm_mem + q*16);
#pragma unroll
            for (int j4 = 0; j4 < 4; j4++){
                float4 m4 = mv[j4];
                p += m4.x*um[j4*4+0] + m4.y*um[j4*4+1] + m4.z*um[j4*4+2] + m4.w*um[j4*4+3];
            }
            sp[q][d] = p;
            __syncthreads();
            if (q == 0){
                float v = a_next + sp[0][d] + sp[1][d] + sp[2][d] + sp[3][d];
                float m = tanh_fast(v);
                sm_mem[d]   = m;
                Mb[t*DD + d] = m;
            }
            a_next = a_pref;
            __syncthreads();
        }
    } else {
        __shared__ __align__(16) float Xs[16][68];
        __shared__ float Hs[16][260];
        int tid  = threadIdx.x;
        int tok0 = (blockIdx.x - BB) * 16;
        for (int i = tid; i < 16*DD; i += 256){
            int tk = i >> 6, k = i & 63;
            Xs[tk][k] = g_emb[(tok0 + tk)*DD + k];
        }
        __syncthreads();
        for (int e = 0; e < EE; e++){
            {
                int f = tid;
                const float* W1e = W1 + (e*DD)*FF + f;
                float w1c[DD];
#pragma unroll
                for (int k = 0; k < DD; k++) w1c[k] = W1e[k*FF];
                float hb = b1[e*FF + f];
#pragma unroll 2
                for (int tk = 0; tk < 16; tk++){
                    float a = hb;
                    const float4* xr = (const float4*)(&Xs[tk][0]);
#pragma unroll
                    for (int k4 = 0; k4 < 16; k4++){
                        float4 xv = xr[k4];
                        a += xv.x*w1c[k4*4+0] + xv.y*w1c[k4*4+1]
                           + xv.z*w1c[k4*4+2] + xv.w*w1c[k4*4+3];
                    }
                    float h = 0.5f * a * (1.0f + erff(a * 0.70710678118654752440f));
                    Hs[tk][f] = h;
                }
            }
            __syncthreads();
            {
                int d = tid & 63, tg = tid >> 6;
                const float* W2e = W2 + (e*FF)*DD + d;
                float bb = b2[e*DD + d];
                float acc0 = bb, acc1 = bb, acc2 = bb, acc3 = bb;
                int t0 = tg*4;
#pragma unroll 4
                for (int f = 0; f < FF; f++){
                    float w = W2e[f*DD];
                    acc0 += Hs[t0+0][f]*w;
                    acc1 += Hs[t0+1][f]*w;
                    acc2 += Hs[t0+2][f]*w;
                    acc3 += Hs[t0+3][f]*w;
                }
                int base = ((tok0 + t0)*EE + e)*DD + d;
                g_eo[base + 0*EE*DD] = acc0;
                g_eo[base + 1*EE*DD] = acc1;
                g_eo[base + 2*EE*DD] = acc2;
                g_eo[base + 3*EE*DD] = acc3;
            }
            __syncthreads();
        }
    }
}

// ---------------- K3: gates + gated sum + residual + LN ----------------
__global__ __launch_bounds__(256) void k_combine(
    const float* __restrict__ Wg, const float* __restrict__ bg,
    const float* __restrict__ ln_g, const float* __restrict__ ln_b)
{
    __shared__ float sWg[DD*EE];
    __shared__ float sg[DD], sb[DD], sbg[EE];
    int tid = threadIdx.x;
    for (int i = tid; i < DD*EE; i += 256) sWg[i] = Wg[i];
    if (tid < DD){ sg[tid] = ln_g[tid]; sb[tid] = ln_b[tid]; }
    if (tid < EE) sbg[tid] = bg[tid];
    __syncthreads();

    int bt = blockIdx.x*256 + tid;
    float gl[EE];
#pragma unroll
    for (int e = 0; e < EE; e++) gl[e] = sbg[e];
    const float4* mr = (const float4*)(g_mem + bt*DD);
#pragma unroll
    for (int k4 = 0; k4 < 16; k4++){
        float4 m4 = mr[k4];
#pragma unroll
        for (int e = 0; e < EE; e++)
            gl[e] += m4.x*sWg[(k4*4+0)*EE+e] + m4.y*sWg[(k4*4+1)*EE+e]
                   + m4.z*sWg[(k4*4+2)*EE+e] + m4.w*sWg[(k4*4+3)*EE+e];
    }
    float mx = gl[0];
#pragma unroll
    for (int e = 1; e < EE; e++) mx = fmaxf(mx, gl[e]);
    float s = 0.f;
#pragma unroll
    for (int e = 0; e < EE; e++){ gl[e] = expf(gl[e]-mx); s += gl[e]; }
    float inv = 1.f/s;
#pragma unroll
    for (int e = 0; e < EE; e++) gl[e] *= inv;

    float acc[DD];
    const float4* er = (const float4*)(g_emb + bt*DD);
#pragma unroll
    for (int i = 0; i < 16; i++){
        float4 v = er[i];
        acc[4*i] = v.x; acc[4*i+1] = v.y; acc[4*i+2] = v.z; acc[4*i+3] = v.w;
    }
#pragma unroll
    for (int e = 0; e < EE; e++){
        float g = gl[e];
        const float4* eor = (const float4*)(g_eo + (bt*EE + e)*DD);
#pragma unroll
        for (int i = 0; i < 16; i++){
            float4 v = eor[i];
            acc[4*i]   += g*v.x; acc[4*i+1] += g*v.y;
            acc[4*i+2] += g*v.z; acc[4*i+3] += g*v.w;
        }
    }
    float mu = 0.f;
#pragma unroll
    for (int i = 0; i < DD; i++) mu += acc[i];
    mu *= (1.f/DD);
    float var = 0.f;
#pragma unroll
    for (int i = 0; i < DD; i++){ float c = acc[i]-mu; var += c*c; }
    var *= (1.f/DD);
    float rs = rsqrtf(var + 1e-5f);
    float4* orow = (float4*)(g_out + bt*DD);
#pragma unroll
    for (int i = 0; i < 16; i++){
        float4 o;
        o.x = sg[4*i+0]*(acc[4*i+0]-mu)*rs + sb[4*i+0];
        o.y = sg[4*i+1]*(acc[4*i+1]-mu)*rs + sb[4*i+1];
        o.z = sg[4*i+2]*(acc[4*i+2]-mu)*rs + sb[4*i+2];
        o.w = sg[4*i+3]*(acc[4*i+3]-mu)*rs + sb[4*i+3];
        orow[i] = o;
    }
}

// ---------------- K4: head GEMM via mma.sync (HMMA bf16, bf16x3 split) ----------------
// CTA tile 128M x 128N, K=64 resident. 8 warps in 2(M) x 4(N) grid, each 64x32.
// Smem: A rows [128][72 bf16] (144B stride), B rows [128 n][72 bf16]; hi+lo variants.
// D = Ahi*Bhi + Ahi*Blo + Alo*Bhi accumulated in fp32 regs.
#define HM_STRIDE 144                     // bytes per row (72 bf16): conflict-free
#define HM_AHI 0
#define HM_ALO (HM_AHI + 128*HM_STRIDE)
#define HM_BHI (HM_ALO + 128*HM_STRIDE)
#define HM_BLO (HM_BHI + 128*HM_STRIDE)
#define HM_TOTAL (HM_BLO + 128*HM_STRIDE) // 73728 B

__device__ __forceinline__ void ldm4(uint32_t a[4], uint32_t addr){
    asm volatile("ldmatrix.sync.aligned.m8n8.x4.shared.b16 {%0,%1,%2,%3}, [%4];"
                 : "=r"(a[0]), "=r"(a[1]), "=r"(a[2]), "=r"(a[3]) : "r"(addr));
}
__device__ __forceinline__ void mma16816(float d[4], const uint32_t a[4], const uint32_t b[2]){
    asm volatile("mma.sync.aligned.m16n8k16.row.col.f32.bf16.bf16.f32 "
                 "{%0,%1,%2,%3}, {%4,%5,%6,%7}, {%8,%9}, {%0,%1,%2,%3};"
                 : "+f"(d[0]), "+f"(d[1]), "+f"(d[2]), "+f"(d[3])
                 : "r"(a[0]), "r"(a[1]), "r"(a[2]), "r"(a[3]), "r"(b[0]), "r"(b[1]));
}

__global__ __launch_bounds__(256) void k_head_mma(
    const float* __restrict__ hW, const float* __restrict__ hb, float* __restrict__ out)
{
    extern __shared__ char smem[];
    uint32_t sb = smem_u32(smem);
    int tid = threadIdx.x;
    int wid = tid >> 5, lane = tid & 31;
    int n0 = blockIdx.x * 128;
    int m0 = blockIdx.y * 128;

    // ---- stage A: g_out[m0+row][k] -> bf16 hi/lo, row-major padded ----
    {
        int row = tid >> 1, kh = (tid & 1) * 32;
        const float4* src = (const float4*)(g_out + (m0 + row)*DD + kh);
#pragma unroll
        for (int j = 0; j < 4; j++){               // 8 floats -> 4 bf16x2 words
            float4 v0 = src[2*j], v1 = src[2*j+1];
            float f[8] = {v0.x,v0.y,v0.z,v0.w,v1.x,v1.y,v1.z,v1.w};
            unsigned hibuf[4], lobuf[4];
#pragma unroll
            for (int q = 0; q < 4; q++){
                float a = f[2*q], b = f[2*q+1];
                float ha = __bfloat162float(__float2bfloat16(a));
                float hbv = __bfloat162float(__float2bfloat16(b));
                hibuf[q] = bf2(ha, hbv);
                lobuf[q] = bf2(a - ha, b - hbv);
            }
            int off = row*HM_STRIDE + kh*2 + j*16;
            *(uint4*)(smem + HM_AHI + off) = *(uint4*)hibuf;
            *(uint4*)(smem + HM_ALO + off) = *(uint4*)lobuf;
        }
    }
    // ---- stage B: hW[k][n0+n] -> smem [n][k] bf16 hi/lo ----
    {
        int n = tid & 127, kh = (tid >> 7) * 32;
        float f[32];
#pragma unroll 8
        for (int j = 0; j < 32; j++)
            f[j] = hW[(size_t)(kh + j)*VV + n0 + n];
#pragma unroll
        for (int g = 0; g < 4; g++){
            unsigned hibuf[4], lobuf[4];
#pragma unroll
            for (int q = 0; q < 4; q++){
                float a = f[g*8 + 2*q], b = f[g*8 + 2*q + 1];
                float ha = __bfloat162float(__float2bfloat16(a));
                float hbv = __bfloat162float(__float2bfloat16(b));
                hibuf[q] = bf2(ha, hbv);
                lobuf[q] = bf2(a - ha, b - hbv);
            }
            int off = n*HM_STRIDE + kh*2 + g*16;
            *(uint4*)(smem + HM_BHI + off) = *(uint4*)hibuf;
            *(uint4*)(smem + HM_BLO + off) = *(uint4*)lobuf;
        }
    }
    __syncthreads();

    int mw = wid & 1, nw = wid >> 1;           // warp -> 64-row half, 32-col quarter
    int g = lane >> 2, tig = lane & 3;
    float d[4][4][4];
#pragma unroll
    for (int mt = 0; mt < 4; mt++)
#pragma unroll
        for (int nt = 0; nt < 4; nt++)
#pragma unroll
            for (int q = 0; q < 4; q++) d[mt][nt][q] = 0.f;

    // ldmatrix per-lane row offset within a 16x16 tile
    int lr = lane & 7, sel = lane >> 3;
    int a_lane_off = (lr + (sel & 1)*8)*HM_STRIDE + ((sel >> 1)*8)*2;

#pragma unroll
    for (int pass = 0; pass < 3; pass++){
        uint32_t Ab = sb + ((pass == 2) ? HM_ALO : HM_AHI);
        uint32_t Bb = sb + ((pass == 1) ? HM_BLO : HM_BHI);
#pragma unroll
        for (int kt = 0; kt < 4; kt++){
            int k0 = kt*16;
            uint32_t a[4][4];
#pragma unroll
            for (int mt = 0; mt < 4; mt++)
                ldm4(a[mt], Ab + (mw*64 + mt*16)*HM_STRIDE + k0*2 + a_lane_off);
            uint32_t b[4][2];
#pragma unroll
            for (int nt = 0; nt < 4; nt++){
                int boff = (nw*32 + nt*8 + g)*HM_STRIDE + (k0 + tig*2)*2;
                b[nt][0] = *(const uint32_t*)(smem + (Bb - sb) + boff);
                b[nt][1] = *(const uint32_t*)(smem + (Bb - sb) + boff + 16);
            }
#pragma unroll
            for (int mt = 0; mt < 4; mt++)
#pragma unroll
                for (int nt = 0; nt < 4; nt++)
                    mma16816(d[mt][nt], a[mt], b[nt]);
        }
    }

    // ---- epilogue: write fp32 logits + bias ----
#pragma unroll
    for (int mt = 0; mt < 4; mt++){
        int row = m0 + mw*64 + mt*16 + g;
#pragma unroll
        for (int nt = 0; nt < 4; nt++){
            int col = n0 + nw*32 + nt*8 + tig*2;
            float2 bv = *(const float2*)(hb + col);
            *(float2*)(out + (size_t)row*VV + col) =
                make_float2(d[mt][nt][0] + bv.x, d[mt][nt][1] + bv.y);
            *(float2*)(out + (size_t)(row + 8)*VV + col) =
                make_float2(d[mt][nt][2] + bv.x, d[mt][nt][3] + bv.y);
        }
    }
}

// ---------------- launch ----------------
extern "C" void kernel_launch(void* const* d_in, const int* in_sizes, int n_in,
                              void* d_out, int out_size)
{
    const int*   x     = (const int*)  d_in[0];
    const float* tab   = (const float*)d_in[1];
    const float* Wm    = (const float*)d_in[2];
    const float* Um    = (const float*)d_in[3];
    const float* bm    = (const float*)d_in[4];
    const float* Wg    = (const float*)d_in[5];
    const float* bg    = (const float*)d_in[6];
    const float* W1    = (const float*)d_in[7];
    const float* b1    = (const float*)d_in[8];
    const float* W2    = (const float*)d_in[9];
    const float* b2    = (const float*)d_in[10];
    const float* ln_g  = (const float*)d_in[11];
    const float* ln_b  = (const float*)d_in[12];
    const float* headW = (const float*)d_in[13];
    const float* headb = (const float*)d_in[14];
    float* out = (float*)d_out;

    k_embA<<<BT, DD>>>(x, tab, Wm, bm);
    k_main<<<BB + BT/16, 256>>>(Um, W1, b1, W2, b2);           // recurrence || FFN
    k_combine<<<BT/256, 256>>>(Wg, bg, ln_g, ln_b);
    cudaFuncSetAttribute(k_head_mma, cudaFuncAttributeMaxDynamicSharedMemorySize, HM_TOTAL);
    k_head_mma<<<dim3(VV/128, BT/128), 256, HM_TOTAL>>>(headW, headb, out);
}

// round 8
// speedup vs baseline: 1.0249x; 1.0230x over previous
#include <cuda_runtime.h>
#include <cuda_bf16.h>
#include <cstdint>
#include <stdint.h>
#include <math.h>

#define VV 16000
#define BB 8
#define TT 1024
#define DD 64
#define FF 256
#define EE 8
#define BT (BB*TT)

// ---------------- device scratch (no allocations allowed) ----------------
__device__ float g_emb[BT*DD];        // 2 MB   embedded tokens
__device__ float g_A[BT*DD];          // 2 MB   x_t @ Wm + bm
__device__ float g_mem[BT*DD];        // 2 MB   recurrent state per step
__device__ float g_eo[BT*EE*DD];      // 16.8 MB per-expert FFN outputs (pre-gate)
__device__ __nv_bfloat16 g_outh[BT*DD];   // 1 MB  LN output, bf16 hi
__device__ __nv_bfloat16 g_outl[BT*DD];   // 1 MB  LN output, bf16 lo (residual)
__device__ __nv_bfloat16 g_hWh[VV*DD];    // 2 MB  head_W^T [n][k] bf16 hi
__device__ __nv_bfloat16 g_hWl[VV*DD];    // 2 MB  head_W^T [n][k] bf16 lo

typedef unsigned long long ull;

__device__ __forceinline__ float tanh_fast(float x){
    float r; asm("tanh.approx.f32 %0, %1;" : "=f"(r) : "f"(x)); return r;
}
// pack two f32 -> one b32 bf16x2: first arg -> low 16 bits
__device__ __forceinline__ unsigned bf2(float lo, float hi){
    unsigned r; asm("cvt.rn.bf16x2.f32 %0, %1, %2;" : "=r"(r) : "f"(hi), "f"(lo)); return r;
}
__device__ __forceinline__ uint32_t smem_u32(const void* p){
    uint32_t a; asm("{ .reg .u64 t; cvta.to.shared.u64 t, %1; cvt.u32.u64 %0, t; }" : "=r"(a) : "l"(p));
    return a;
}
__device__ __forceinline__ void cpa16(uint32_t s, const void* g){
    asm volatile("cp.async.cg.shared.global [%0], [%1], 16;" :: "r"(s), "l"(g));
}
__device__ __forceinline__ void cpa_commit(){ asm volatile("cp.async.commit_group;"); }
__device__ __forceinline__ void cpa_wait1(){ asm volatile("cp.async.wait_group 1;"); }

// ---------------- K0: head_W -> transposed bf16 hi/lo ----------------
__global__ __launch_bounds__(256) void k_cvt_w(const float* __restrict__ hW)
{
    __shared__ float tile[64][132];
    int n0 = blockIdx.x * 128;
    int tid = threadIdx.x;
    for (int idx = tid; idx < 64*128; idx += 256){
        int k = idx >> 7, n = idx & 127;
        tile[k][n] = hW[(size_t)k*VV + n0 + n];
    }
    __syncthreads();
    int r = tid >> 1, k0 = (tid & 1) * 32;
    unsigned hw[16], lw[16];
#pragma unroll
    for (int q = 0; q < 16; q++){
        float a = tile[k0 + 2*q][r], b = tile[k0 + 2*q + 1][r];
        float ha = __bfloat162float(__float2bfloat16(a));
        float hb = __bfloat162float(__float2bfloat16(b));
        hw[q] = bf2(ha, hb);
        lw[q] = bf2(a - ha, b - hb);
    }
    uint4* dh = (uint4*)(g_hWh + (size_t)(n0 + r)*DD + k0);
    uint4* dl = (uint4*)(g_hWl + (size_t)(n0 + r)*DD + k0);
#pragma unroll
    for (int j = 0; j < 4; j++){ dh[j] = ((uint4*)hw)[j]; dl[j] = ((uint4*)lw)[j]; }
}

// ---------------- K1: embedding gather + A = emb @ Wm + bm ----------------
__global__ void k_embA(const int* __restrict__ x, const float* __restrict__ tab,
                       const float* __restrict__ Wm, const float* __restrict__ bm)
{
    int bt = blockIdx.x;
    int d  = threadIdx.x;
    __shared__ __align__(16) float xs[DD];
    float v = tab[x[bt]*DD + d];
    xs[d] = v;
    g_emb[bt*DD + d] = v;
    __syncthreads();
    float acc = bm[d];
    const float4* xr = (const float4*)xs;
#pragma unroll
    for (int k4 = 0; k4 < 16; k4++){
        float4 m4 = xr[k4];
        acc += m4.x*Wm[(k4*4+0)*DD+d] + m4.y*Wm[(k4*4+1)*DD+d]
             + m4.z*Wm[(k4*4+2)*DD+d] + m4.w*Wm[(k4*4+3)*DD+d];
    }
    g_A[bt*DD + d] = acc;
}

// ---------------- K2: recurrence (blocks 0..7) || expert FFN (blocks 8..) ----------------
__global__ __launch_bounds__(256, 2) void k_main(
    const float* __restrict__ Um,
    const float* __restrict__ W1, const float* __restrict__ b1,
    const float* __restrict__ W2, const float* __restrict__ b2)
{
    if (blockIdx.x < BB) {
        __shared__ __align__(16) float sm_mem[DD];
        __shared__ float sp[4][DD];
        int b   = blockIdx.x;
        int tid = threadIdx.x;
        int d = tid & 63, q = tid >> 6;
        float um[16];
#pragma unroll
        for (int j = 0; j < 16; j++) um[j] = Um[(q*16 + j)*DD + d];
        if (q == 0) sm_mem[d] = 0.f;
        __syncthreads();
        const float* Ab = g_A  + b*TT*DD;
        float*       Mb = g_mem + b*TT*DD;
        float a_next = (q == 0) ? Ab[d] : 0.f;
        for (int t = 0; t < TT; t++){
            float a_pref = 0.f;
            if (q == 0 && t + 1 < TT) a_pref = Ab[(t+1)*DD + d];
            float p = 0.f;
            const float4* mv = (const float4*)(sm_mem + q*16);
#pragma unroll
            for (int j4 = 0; j4 < 4; j4++){
                float4 m4 = mv[j4];
                p += m4.x*um[j4*4+0] + m4.y*um[j4*4+1] + m4.z*um[j4*4+2] + m4.w*um[j4*4+3];
            }
            sp[q][d] = p;
            __syncthreads();
            if (q == 0){
                float v = a_next + sp[0][d] + sp[1][d] + sp[2][d] + sp[3][d];
                float m = tanh_fast(v);
                sm_mem[d]   = m;
                Mb[t*DD + d] = m;
            }
            a_next = a_pref;
            __syncthreads();
        }
    } else {
        __shared__ __align__(16) float Xs[16][68];
        __shared__ float Hs[16][260];
        int tid  = threadIdx.x;
        int tok0 = (blockIdx.x - BB) * 16;
        for (int i = tid; i < 16*DD; i += 256){
            int tk = i >> 6, k = i & 63;
            Xs[tk][k] = g_emb[(tok0 + tk)*DD + k];
        }
        __syncthreads();
        for (int e = 0; e < EE; e++){
            {
                int f = tid;
                const float* W1e = W1 + (e*DD)*FF + f;
                float w1c[DD];
#pragma unroll
                for (int k = 0; k < DD; k++) w1c[k] = W1e[k*FF];
                float hb = b1[e*FF + f];
#pragma unroll 2
                for (int tk = 0; tk < 16; tk++){
                    float a = hb;
                    const float4* xr = (const float4*)(&Xs[tk][0]);
#pragma unroll
                    for (int k4 = 0; k4 < 16; k4++){
                        float4 xv = xr[k4];
                        a += xv.x*w1c[k4*4+0] + xv.y*w1c[k4*4+1]
                           + xv.z*w1c[k4*4+2] + xv.w*w1c[k4*4+3];
                    }
                    float h = 0.5f * a * (1.0f + erff(a * 0.70710678118654752440f));
                    Hs[tk][f] = h;
                }
            }
            __syncthreads();
            {
                int d = tid & 63, tg = tid >> 6;
                const float* W2e = W2 + (e*FF)*DD + d;
                float bb = b2[e*DD + d];
                float acc0 = bb, acc1 = bb, acc2 = bb, acc3 = bb;
                int t0 = tg*4;
#pragma unroll 4
                for (int f = 0; f < FF; f++){
                    float w = W2e[f*DD];
                    acc0 += Hs[t0+0][f]*w;
                    acc1 += Hs[t0+1][f]*w;
                    acc2 += Hs[t0+2][f]*w;
                    acc3 += Hs[t0+3][f]*w;
                }
                int base = ((tok0 + t0)*EE + e)*DD + d;
                g_eo[base + 0*EE*DD] = acc0;
                g_eo[base + 1*EE*DD] = acc1;
                g_eo[base + 2*EE*DD] = acc2;
                g_eo[base + 3*EE*DD] = acc3;
            }
            __syncthreads();
        }
    }
}

// ---------------- K3: gates + gated sum + residual + LN -> bf16 hi/lo ----------------
__global__ __launch_bounds__(256) void k_combine(
    const float* __restrict__ Wg, const float* __restrict__ bg,
    const float* __restrict__ ln_g, const float* __restrict__ ln_b)
{
    __shared__ float sWg[DD*EE];
    __shared__ float sg[DD], sb[DD], sbg[EE];
    int tid = threadIdx.x;
    for (int i = tid; i < DD*EE; i += 256) sWg[i] = Wg[i];
    if (tid < DD){ sg[tid] = ln_g[tid]; sb[tid] = ln_b[tid]; }
    if (tid < EE) sbg[tid] = bg[tid];
    __syncthreads();

    int bt = blockIdx.x*256 + tid;
    float gl[EE];
#pragma unroll
    for (int e = 0; e < EE; e++) gl[e] = sbg[e];
    const float4* mr = (const float4*)(g_mem + bt*DD);
#pragma unroll
    for (int k4 = 0; k4 < 16; k4++){
        float4 m4 = mr[k4];
#pragma unroll
        for (int e = 0; e < EE; e++)
            gl[e] += m4.x*sWg[(k4*4+0)*EE+e] + m4.y*sWg[(k4*4+1)*EE+e]
                   + m4.z*sWg[(k4*4+2)*EE+e] + m4.w*sWg[(k4*4+3)*EE+e];
    }
    float mx = gl[0];
#pragma unroll
    for (int e = 1; e < EE; e++) mx = fmaxf(mx, gl[e]);
    float s = 0.f;
#pragma unroll
    for (int e = 0; e < EE; e++){ gl[e] = expf(gl[e]-mx); s += gl[e]; }
    float inv = 1.f/s;
#pragma unroll
    for (int e = 0; e < EE; e++) gl[e] *= inv;

    float acc[DD];
    const float4* er = (const float4*)(g_emb + bt*DD);
#pragma unroll
    for (int i = 0; i < 16; i++){
        float4 v = er[i];
        acc[4*i] = v.x; acc[4*i+1] = v.y; acc[4*i+2] = v.z; acc[4*i+3] = v.w;
    }
#pragma unroll
    for (int e = 0; e < EE; e++){
        float g = gl[e];
        const float4* eor = (const float4*)(g_eo + (bt*EE + e)*DD);
#pragma unroll
        for (int i = 0; i < 16; i++){
            float4 v = eor[i];
            acc[4*i]   += g*v.x; acc[4*i+1] += g*v.y;
            acc[4*i+2] += g*v.z; acc[4*i+3] += g*v.w;
        }
    }
    float mu = 0.f;
#pragma unroll
    for (int i = 0; i < DD; i++) mu += acc[i];
    mu *= (1.f/DD);
    float var = 0.f;
#pragma unroll
    for (int i = 0; i < DD; i++){ float c = acc[i]-mu; var += c*c; }
    var *= (1.f/DD);
    float rs = rsqrtf(var + 1e-5f);
    unsigned hw[32], lw[32];
#pragma unroll
    for (int i = 0; i < 32; i++){
        float o0 = sg[2*i+0]*(acc[2*i+0]-mu)*rs + sb[2*i+0];
        float o1 = sg[2*i+1]*(acc[2*i+1]-mu)*rs + sb[2*i+1];
        float h0 = __bfloat162float(__float2bfloat16(o0));
        float h1 = __bfloat162float(__float2bfloat16(o1));
        hw[i] = bf2(h0, h1);
        lw[i] = bf2(o0 - h0, o1 - h1);
    }
    uint4* dh = (uint4*)(g_outh + (size_t)bt*DD);
    uint4* dl = (uint4*)(g_outl + (size_t)bt*DD);
#pragma unroll
    for (int j = 0; j < 8; j++){ dh[j] = ((uint4*)hw)[j]; dl[j] = ((uint4*)lw)[j]; }
}

// ---------------- K4: head GEMM, B-resident + double-buffered A (HMMA bf16x3) ----------------
// grid (125 n-blocks, 4 m-groups); each CTA: B tile resident, loops 16 m-tiles.
// smem rows padded to 144 B (72 bf16) for conflict-free ldmatrix/LDS.
#define HM_STRIDE 144
#define HM_TILE   (128*HM_STRIDE)        // 18432 B
#define SB_BHI    0
#define SB_BLO    HM_TILE
#define SB_A      (2*HM_TILE)            // A buffers: [buf][hi/lo]
#define HM_TOTAL  (SB_A + 2*2*HM_TILE)   // 110592 B
#define NMT 16

__device__ __forceinline__ void ldm4(uint32_t a[4], uint32_t addr){
    asm volatile("ldmatrix.sync.aligned.m8n8.x4.shared.b16 {%0,%1,%2,%3}, [%4];"
                 : "=r"(a[0]), "=r"(a[1]), "=r"(a[2]), "=r"(a[3]) : "r"(addr));
}
__device__ __forceinline__ void mma16816(float d[4], const uint32_t a[4], const uint32_t b[2]){
    asm volatile("mma.sync.aligned.m16n8k16.row.col.f32.bf16.bf16.f32 "
                 "{%0,%1,%2,%3}, {%4,%5,%6,%7}, {%8,%9}, {%0,%1,%2,%3};"
                 : "+f"(d[0]), "+f"(d[1]), "+f"(d[2]), "+f"(d[3])
                 : "r"(a[0]), "r"(a[1]), "r"(a[2]), "r"(a[3]), "r"(b[0]), "r"(b[1]));
}

__global__ __launch_bounds__(256) void k_head_mma(
    const float* __restrict__ hb, float* __restrict__ out)
{
    extern __shared__ char smem[];
    uint32_t sbm = smem_u32(smem);
    int tid = threadIdx.x;
    int wid = tid >> 5, lane = tid & 31;
    int n0 = blockIdx.x * 128;
    int mt0 = blockIdx.y * NMT;          // first m-tile of this CTA

    int var = tid >> 7, row = tid & 127; // copy helper: 2 variants x 128 rows

    // ---- group 0: B tile (hi+lo), plus A tile 0 ----
    {
        const __nv_bfloat16* src = (var ? g_hWl : g_hWh) + (size_t)(n0 + row)*DD;
        uint32_t dst = sbm + (var ? SB_BLO : SB_BHI) + row*HM_STRIDE;
#pragma unroll
        for (int j = 0; j < 8; j++) cpa16(dst + j*16, (const char*)src + j*16);
    }
    {
        const __nv_bfloat16* src = (var ? g_outl : g_outh) + (size_t)(mt0*128 + row)*DD;
        uint32_t dst = sbm + SB_A + var*HM_TILE + row*HM_STRIDE;
#pragma unroll
        for (int j = 0; j < 8; j++) cpa16(dst + j*16, (const char*)src + j*16);
    }
    cpa_commit();
    // ---- group 1: A tile 1 ----
    {
        const __nv_bfloat16* src = (var ? g_outl : g_outh) + (size_t)((mt0+1)*128 + row)*DD;
        uint32_t dst = sbm + SB_A + 2*HM_TILE + var*HM_TILE + row*HM_STRIDE;
#pragma unroll
        for (int j = 0; j < 8; j++) cpa16(dst + j*16, (const char*)src + j*16);
    }
    cpa_commit();

    int mw = wid & 1, nw = wid >> 1;
    int g = lane >> 2, tig = lane & 3;
    int lr = lane & 7, sel = lane >> 3;
    int a_lane_off = (lr + (sel & 1)*8)*HM_STRIDE + ((sel >> 1)*8)*2;

    // hoisted bias (cols fixed for whole CTA)
    float2 bv[4];
#pragma unroll
    for (int nt = 0; nt < 4; nt++)
        bv[nt] = *(const float2*)(hb + n0 + nw*32 + nt*8 + tig*2);

    for (int i = 0; i < NMT; i++){
        cpa_wait1();
        __syncthreads();

        float d[4][4][4];
#pragma unroll
        for (int mt = 0; mt < 4; mt++)
#pragma unroll
            for (int nt = 0; nt < 4; nt++)
#pragma unroll
                for (int q = 0; q < 4; q++) d[mt][nt][q] = 0.f;

        uint32_t abase = sbm + SB_A + (i & 1)*2*HM_TILE;
#pragma unroll
        for (int pass = 0; pass < 3; pass++){
            uint32_t Ab = abase + ((pass == 2) ? HM_TILE : 0);
            uint32_t Boff = (pass == 1) ? SB_BLO : SB_BHI;
#pragma unroll
            for (int kt = 0; kt < 4; kt++){
                int k0 = kt*16;
                uint32_t a[4][4];
#pragma unroll
                for (int mt = 0; mt < 4; mt++)
                    ldm4(a[mt], Ab + (mw*64 + mt*16)*HM_STRIDE + k0*2 + a_lane_off);
                uint32_t b[4][2];
#pragma unroll
                for (int nt = 0; nt < 4; nt++){
                    int boff = Boff + (nw*32 + nt*8 + g)*HM_STRIDE + (k0 + tig*2)*2;
                    b[nt][0] = *(const uint32_t*)(smem + boff);
                    b[nt][1] = *(const uint32_t*)(smem + boff + 16);
                }
#pragma unroll
                for (int mt = 0; mt < 4; mt++)
#pragma unroll
                    for (int nt = 0; nt < 4; nt++)
                        mma16816(d[mt][nt], a[mt], b[nt]);
            }
        }
        __syncthreads();

        // prefetch A tile i+2 into the buffer just freed
        if (i + 2 < NMT){
            const __nv_bfloat16* src = (var ? g_outl : g_outh) + (size_t)((mt0+i+2)*128 + row)*DD;
            uint32_t dst = sbm + SB_A + (i & 1)*2*HM_TILE + var*HM_TILE + row*HM_STRIDE;
#pragma unroll
            for (int j = 0; j < 8; j++) cpa16(dst + j*16, (const char*)src + j*16);
        }
        cpa_commit();

        // epilogue for tile i
        int m0 = (mt0 + i) * 128;
#pragma unroll
        for (int mt = 0; mt < 4; mt++){
            int r = m0 + mw*64 + mt*16 + g;
#pragma unroll
            for (int nt = 0; nt < 4; nt++){
                int col = n0 + nw*32 + nt*8 + tig*2;
                *(float2*)(out + (size_t)r*VV + col) =
                    make_float2(d[mt][nt][0] + bv[nt].x, d[mt][nt][1] + bv[nt].y);
                *(float2*)(out + (size_t)(r + 8)*VV + col) =
                    make_float2(d[mt][nt][2] + bv[nt].x, d[mt][nt][3] + bv[nt].y);
            }
        }
    }
}

// ---------------- launch ----------------
extern "C" void kernel_launch(void* const* d_in, const int* in_sizes, int n_in,
                              void* d_out, int out_size)
{
    const int*   x     = (const int*)  d_in[0];
    const float* tab   = (const float*)d_in[1];
    const float* Wm    = (const float*)d_in[2];
    const float* Um    = (const float*)d_in[3];
    const float* bm    = (const float*)d_in[4];
    const float* Wg    = (const float*)d_in[5];
    const float* bg    = (const float*)d_in[6];
    const float* W1    = (const float*)d_in[7];
    const float* b1    = (const float*)d_in[8];
    const float* W2    = (const float*)d_in[9];
    const float* b2    = (const float*)d_in[10];
    const float* ln_g  = (const float*)d_in[11];
    const float* ln_b  = (const float*)d_in[12];
    const float* headW = (const float*)d_in[13];
    const float* headb = (const float*)d_in[14];
    float* out = (float*)d_out;

    k_cvt_w<<<VV/128, 256>>>(headW);                            // head_W -> bf16 hi/lo (n-major)
    k_embA<<<BT, DD>>>(x, tab, Wm, bm);
    k_main<<<BB + BT/16, 256>>>(Um, W1, b1, W2, b2);           // recurrence || FFN
    k_combine<<<BT/256, 256>>>(Wg, bg, ln_g, ln_b);
    cudaFuncSetAttribute(k_head_mma, cudaFuncAttributeMaxDynamicSharedMemorySize, HM_TOTAL);
    k_head_mma<<<dim3(VV/128, BT/(128*NMT)), 256, HM_TOTAL>>>(headb, out);
}

// round 11
// speedup vs baseline: 1.0871x; 1.0606x over previous
#include <cuda_runtime.h>
#include <cuda_bf16.h>
#include <cstdint>
#include <stdint.h>
#include <math.h>

#define VV 16000
#define BB 8
#define TT 1024
#define DD 64
#define FF 256
#define EE 8
#define BT (BB*TT)

// ---------------- device scratch (no allocations allowed) ----------------
__device__ float g_emb[BT*DD];        // 2 MB   embedded tokens
__device__ float g_A[BT*DD];          // 2 MB   x_t @ Wm + bm
__device__ float g_mem[BT*DD];        // 2 MB   recurrent state per step
__device__ float g_eo[BT*EE*DD];      // 16.8 MB per-expert FFN outputs (pre-gate)
__device__ __nv_bfloat16 g_outh[BT*DD];   // 1 MB  LN output, bf16 hi
__device__ __nv_bfloat16 g_outl[BT*DD];   // 1 MB  LN output, bf16 lo (residual)
__device__ __nv_bfloat16 g_hWh[VV*DD];    // 2 MB  head_W^T [n][k] bf16 hi
__device__ __nv_bfloat16 g_hWl[VV*DD];    // 2 MB  head_W^T [n][k] bf16 lo

typedef unsigned long long ull;

__device__ __forceinline__ float tanh_fast(float x){
    float r; asm("tanh.approx.f32 %0, %1;" : "=f"(r) : "f"(x)); return r;
}
// pack two f32 -> one b32 bf16x2: first arg -> low 16 bits
__device__ __forceinline__ unsigned bf2(float lo, float hi){
    unsigned r; asm("cvt.rn.bf16x2.f32 %0, %1, %2;" : "=r"(r) : "f"(hi), "f"(lo)); return r;
}
__device__ __forceinline__ uint32_t smem_u32(const void* p){
    uint32_t a; asm("{ .reg .u64 t; cvta.to.shared.u64 t, %1; cvt.u32.u64 %0, t; }" : "=r"(a) : "l"(p));
    return a;
}
__device__ __forceinline__ void cpa16(uint32_t s, const void* g){
    asm volatile("cp.async.cg.shared.global [%0], [%1], 16;" :: "r"(s), "l"(g));
}
__device__ __forceinline__ void cpa_commit(){ asm volatile("cp.async.commit_group;"); }
__device__ __forceinline__ void cpa_wait1(){ asm volatile("cp.async.wait_group 1;"); }

// ---------------- K0: head_W -> transposed bf16 hi/lo ----------------
__global__ __launch_bounds__(256) void k_cvt_w(const float* __restrict__ hW)
{
    __shared__ float tile[64][132];
    int n0 = blockIdx.x * 128;
    int tid = threadIdx.x;
    for (int idx = tid; idx < 64*128; idx += 256){
        int k = idx >> 7, n = idx & 127;
        tile[k][n] = hW[(size_t)k*VV + n0 + n];
    }
    __syncthreads();
    int r = tid >> 1, k0 = (tid & 1) * 32;
    unsigned hw[16], lw[16];
#pragma unroll
    for (int q = 0; q < 16; q++){
        float a = tile[k0 + 2*q][r], b = tile[k0 + 2*q + 1][r];
        float ha = __bfloat162float(__float2bfloat16(a));
        float hb = __bfloat162float(__float2bfloat16(b));
        hw[q] = bf2(ha, hb);
        lw[q] = bf2(a - ha, b - hb);
    }
    uint4* dh = (uint4*)(g_hWh + (size_t)(n0 + r)*DD + k0);
    uint4* dl = (uint4*)(g_hWl + (size_t)(n0 + r)*DD + k0);
#pragma unroll
    for (int j = 0; j < 4; j++){ dh[j] = ((uint4*)hw)[j]; dl[j] = ((uint4*)lw)[j]; }
}

// ---------------- K1: embedding gather + A = emb @ Wm + bm ----------------
__global__ void k_embA(const int* __restrict__ x, const float* __restrict__ tab,
                       const float* __restrict__ Wm, const float* __restrict__ bm)
{
    int bt = blockIdx.x;
    int d  = threadIdx.x;
    __shared__ __align__(16) float xs[DD];
    float v = tab[x[bt]*DD + d];
    xs[d] = v;
    g_emb[bt*DD + d] = v;
    __syncthreads();
    float acc = bm[d];
    const float4* xr = (const float4*)xs;
#pragma unroll
    for (int k4 = 0; k4 < 16; k4++){
        float4 m4 = xr[k4];
        acc += m4.x*Wm[(k4*4+0)*DD+d] + m4.y*Wm[(k4*4+1)*DD+d]
             + m4.z*Wm[(k4*4+2)*DD+d] + m4.w*Wm[(k4*4+3)*DD+d];
    }
    g_A[bt*DD + d] = acc;
}

// ---------------- K2: recurrence (blocks 0..7) || expert FFN (blocks 8..) ----------------
__global__ __launch_bounds__(256, 2) void k_main(
    const float* __restrict__ Um,
    const float* __restrict__ W1, const float* __restrict__ b1,
    const float* __restrict__ W2, const float* __restrict__ b2)
{
    if (blockIdx.x < BB) {
        __shared__ __align__(16) float sm_mem[DD];
        __shared__ float sp[4][DD];
        int b   = blockIdx.x;
        int tid = threadIdx.x;
        int d = tid & 63, q = tid >> 6;
        float um[16];
#pragma unroll
        for (int j = 0; j < 16; j++) um[j] = Um[(q*16 + j)*DD + d];
        if (q == 0) sm_mem[d] = 0.f;
        __syncthreads();
        const float* Ab = g_A  + b*TT*DD;
        float*       Mb = g_mem + b*TT*DD;
        float a_next = (q == 0) ? Ab[d] : 0.f;
        for (int t = 0; t < TT; t++){
            float a_pref = 0.f;
            if (q == 0 && t + 1 < TT) a_pref = Ab[(t+1)*DD + d];
            float p = 0.f;
            const float4* mv = (const float4*)(sm_mem + q*16);
#pragma unroll
            for (int j4 = 0; j4 < 4; j4++){
                float4 m4 = mv[j4];
                p += m4.x*um[j4*4+0] + m4.y*um[j4*4+1] + m4.z*um[j4*4+2] + m4.w*um[j4*4+3];
            }
            sp[q][d] = p;
            __syncthreads();
            if (q == 0){
                float v = a_next + sp[0][d] + sp[1][d] + sp[2][d] + sp[3][d];
                float m = tanh_fast(v);
                sm_mem[d]   = m;
                Mb[t*DD + d] = m;
            }
            a_next = a_pref;
            __syncthreads();
        }
    } else {
        __shared__ __align__(16) float Xs[16][68];
        __shared__ float Hs[16][260];
        int tid  = threadIdx.x;
        int tok0 = (blockIdx.x - BB) * 16;
        for (int i = tid; i < 16*DD; i += 256){
            int tk = i >> 6, k = i & 63;
            Xs[tk][k] = g_emb[(tok0 + tk)*DD + k];
        }
        __syncthreads();
        for (int e = 0; e < EE; e++){
            {
                int f = tid;
                const float* W1e = W1 + (e*DD)*FF + f;
                float w1c[DD];
#pragma unroll
                for (int k = 0; k < DD; k++) w1c[k] = W1e[k*FF];
                float hb = b1[e*FF + f];
#pragma unroll 2
                for (int tk = 0; tk < 16; tk++){
                    float a = hb;
                    const float4* xr = (const float4*)(&Xs[tk][0]);
#pragma unroll
                    for (int k4 = 0; k4 < 16; k4++){
                        float4 xv = xr[k4];
                        a += xv.x*w1c[k4*4+0] + xv.y*w1c[k4*4+1]
                           + xv.z*w1c[k4*4+2] + xv.w*w1c[k4*4+3];
                    }
                    float h = 0.5f * a * (1.0f + erff(a * 0.70710678118654752440f));
                    Hs[tk][f] = h;
                }
            }
            __syncthreads();
            {
                int d = tid & 63, tg = tid >> 6;
                const float* W2e = W2 + (e*FF)*DD + d;
                float bb = b2[e*DD + d];
                float acc0 = bb, acc1 = bb, acc2 = bb, acc3 = bb;
                int t0 = tg*4;
#pragma unroll 4
                for (int f = 0; f < FF; f++){
                    float w = W2e[f*DD];
                    acc0 += Hs[t0+0][f]*w;
                    acc1 += Hs[t0+1][f]*w;
                    acc2 += Hs[t0+2][f]*w;
                    acc3 += Hs[t0+3][f]*w;
                }
                int base = ((tok0 + t0)*EE + e)*DD + d;
                g_eo[base + 0*EE*DD] = acc0;
                g_eo[base + 1*EE*DD] = acc1;
                g_eo[base + 2*EE*DD] = acc2;
                g_eo[base + 3*EE*DD] = acc3;
            }
            __syncthreads();
        }
    }
}

// ---------------- K3: gates + gated sum + residual + LN -> bf16 hi/lo ----------------
__global__ __launch_bounds__(256) void k_combine(
    const float* __restrict__ Wg, const float* __restrict__ bg,
    const float* __restrict__ ln_g, const float* __restrict__ ln_b)
{
    __shared__ float sWg[DD*EE];
    __shared__ float sg[DD], sb[DD], sbg[EE];
    int tid = threadIdx.x;
    for (int i = tid; i < DD*EE; i += 256) sWg[i] = Wg[i];
    if (tid < DD){ sg[tid] = ln_g[tid]; sb[tid] = ln_b[tid]; }
    if (tid < EE) sbg[tid] = bg[tid];
    __syncthreads();

    int bt = blockIdx.x*256 + tid;
    float gl[EE];
#pragma unroll
    for (int e = 0; e < EE; e++) gl[e] = sbg[e];
    const float4* mr = (const float4*)(g_mem + bt*DD);
#pragma unroll
    for (int k4 = 0; k4 < 16; k4++){
        float4 m4 = mr[k4];
#pragma unroll
        for (int e = 0; e < EE; e++)
            gl[e] += m4.x*sWg[(k4*4+0)*EE+e] + m4.y*sWg[(k4*4+1)*EE+e]
                   + m4.z*sWg[(k4*4+2)*EE+e] + m4.w*sWg[(k4*4+3)*EE+e];
    }
    float mx = gl[0];
#pragma unroll
    for (int e = 1; e < EE; e++) mx = fmaxf(mx, gl[e]);
    float s = 0.f;
#pragma unroll
    for (int e = 0; e < EE; e++){ gl[e] = expf(gl[e]-mx); s += gl[e]; }
    float inv = 1.f/s;
#pragma unroll
    for (int e = 0; e < EE; e++) gl[e] *= inv;

    float acc[DD];
    const float4* er = (const float4*)(g_emb + bt*DD);
#pragma unroll
    for (int i = 0; i < 16; i++){
        float4 v = er[i];
        acc[4*i] = v.x; acc[4*i+1] = v.y; acc[4*i+2] = v.z; acc[4*i+3] = v.w;
    }
#pragma unroll
    for (int e = 0; e < EE; e++){
        float g = gl[e];
        const float4* eor = (const float4*)(g_eo + (bt*EE + e)*DD);
#pragma unroll
        for (int i = 0; i < 16; i++){
            float4 v = eor[i];
            acc[4*i]   += g*v.x; acc[4*i+1] += g*v.y;
            acc[4*i+2] += g*v.z; acc[4*i+3] += g*v.w;
        }
    }
    float mu = 0.f;
#pragma unroll
    for (int i = 0; i < DD; i++) mu += acc[i];
    mu *= (1.f/DD);
    float var = 0.f;
#pragma unroll
    for (int i = 0; i < DD; i++){ float c = acc[i]-mu; var += c*c; }
    var *= (1.f/DD);
    float rs = rsqrtf(var + 1e-5f);
    unsigned hw[32], lw[32];
#pragma unroll
    for (int i = 0; i < 32; i++){
        float o0 = sg[2*i+0]*(acc[2*i+0]-mu)*rs + sb[2*i+0];
        float o1 = sg[2*i+1]*(acc[2*i+1]-mu)*rs + sb[2*i+1];
        float h0 = __bfloat162float(__float2bfloat16(o0));
        float h1 = __bfloat162float(__float2bfloat16(o1));
        hw[i] = bf2(h0, h1);
        lw[i] = bf2(o0 - h0, o1 - h1);
    }
    uint4* dh = (uint4*)(g_outh + (size_t)bt*DD);
    uint4* dl = (uint4*)(g_outl + (size_t)bt*DD);
#pragma unroll
    for (int j = 0; j < 8; j++){ dh[j] = ((uint4*)hw)[j]; dl[j] = ((uint4*)lw)[j]; }
}

// ---------------- K4: head GEMM, B-resident, 16 warps/CTA (HMMA bf16x3) ----------------
// grid (125 n-blocks, 8 m-groups); each CTA: B tile resident, loops 8 m-tiles.
// 512 threads = 16 warps in 4(M) x 4(N); warp tile 32x32 -> d[2][4][4] (32 regs).
#define HM_STRIDE 144
#define HM_TILE   (128*HM_STRIDE)        // 18432 B
#define SB_BHI    0
#define SB_BLO    HM_TILE
#define SB_A      (2*HM_TILE)            // A buffers: [buf][hi/lo]
#define HM_TOTAL  (SB_A + 2*2*HM_TILE)   // 110592 B
#define NMT 8

__device__ __forceinline__ void ldm4(uint32_t a[4], uint32_t addr){
    asm volatile("ldmatrix.sync.aligned.m8n8.x4.shared.b16 {%0,%1,%2,%3}, [%4];"
                 : "=r"(a[0]), "=r"(a[1]), "=r"(a[2]), "=r"(a[3]) : "r"(addr));
}
__device__ __forceinline__ void mma16816(float d[4], const uint32_t a[4], const uint32_t b[2]){
    asm volatile("mma.sync.aligned.m16n8k16.row.col.f32.bf16.bf16.f32 "
                 "{%0,%1,%2,%3}, {%4,%5,%6,%7}, {%8,%9}, {%0,%1,%2,%3};"
                 : "+f"(d[0]), "+f"(d[1]), "+f"(d[2]), "+f"(d[3])
                 : "r"(a[0]), "r"(a[1]), "r"(a[2]), "r"(a[3]), "r"(b[0]), "r"(b[1]));
}

__global__ __launch_bounds__(512) void k_head_mma(
    const float* __restrict__ hb, float* __restrict__ out)
{
    extern __shared__ char smem[];
    uint32_t sbm = smem_u32(smem);
    int tid = threadIdx.x;
    int wid = tid >> 5, lane = tid & 31;
    int n0 = blockIdx.x * 128;
    int mt0 = blockIdx.y * NMT;          // first m-tile of this CTA

    // copy helper: 512 threads cover 2 variants x 128 rows x 2 half-rows (64B each)
    int var  = (tid >> 7) & 1;
    int row  = tid & 127;
    int half = tid >> 8;                 // 0/1 -> first/second 64B of the 128B row

    // ---- group 0: B tile (hi+lo) + A tile 0 ----
    {
        const __nv_bfloat16* src = (var ? g_hWl : g_hWh) + (size_t)(n0 + row)*DD + half*32;
        uint32_t dst = sbm + (var ? SB_BLO : SB_BHI) + row*HM_STRIDE + half*64;
#pragma unroll
        for (int j = 0; j < 4; j++) cpa16(dst + j*16, (const char*)src + j*16);
    }
    {
        const __nv_bfloat16* src = (var ? g_outl : g_outh) + (size_t)(mt0*128 + row)*DD + half*32;
        uint32_t dst = sbm + SB_A + var*HM_TILE + row*HM_STRIDE + half*64;
#pragma unroll
        for (int j = 0; j < 4; j++) cpa16(dst + j*16, (const char*)src + j*16);
    }
    cpa_commit();
    // ---- group 1: A tile 1 ----
    {
        const __nv_bfloat16* src = (var ? g_outl : g_outh) + (size_t)((mt0+1)*128 + row)*DD + half*32;
        uint32_t dst = sbm + SB_A + 2*HM_TILE + var*HM_TILE + row*HM_STRIDE + half*64;
#pragma unroll
        for (int j = 0; j < 4; j++) cpa16(dst + j*16, (const char*)src + j*16);
    }
    cpa_commit();

    int mw = wid & 3, nw = wid >> 2;     // 4x4 warp grid; warp tile 32(M) x 32(N)
    int g = lane >> 2, tig = lane & 3;
    int lr = lane & 7, sel = lane >> 3;
    int a_lane_off = (lr + (sel & 1)*8)*HM_STRIDE + ((sel >> 1)*8)*2;

    // hoisted bias (cols fixed for whole CTA)
    float2 bv[4];
#pragma unroll
    for (int nt = 0; nt < 4; nt++)
        bv[nt] = *(const float2*)(hb + n0 + nw*32 + nt*8 + tig*2);

    for (int i = 0; i < NMT; i++){
        cpa_wait1();
        __syncthreads();

        float d[2][4][4];
#pragma unroll
        for (int mt = 0; mt < 2; mt++)
#pragma unroll
            for (int nt = 0; nt < 4; nt++)
#pragma unroll
                for (int q = 0; q < 4; q++) d[mt][nt][q] = 0.f;

        uint32_t abase = sbm + SB_A + (i & 1)*2*HM_TILE;
#pragma unroll
        for (int pass = 0; pass < 3; pass++){
            uint32_t Ab = abase + ((pass == 2) ? HM_TILE : 0);
            uint32_t Boff = (pass == 1) ? SB_BLO : SB_BHI;
#pragma unroll
            for (int kt = 0; kt < 4; kt++){
                int k0 = kt*16;
                uint32_t a[2][4];
#pragma unroll
                for (int mt = 0; mt < 2; mt++)
                    ldm4(a[mt], Ab + (mw*32 + mt*16)*HM_STRIDE + k0*2 + a_lane_off);
                uint32_t b[4][2];
#pragma unroll
                for (int nt = 0; nt < 4; nt++){
                    int boff = Boff + (nw*32 + nt*8 + g)*HM_STRIDE + (k0 + tig*2)*2;
                    b[nt][0] = *(const uint32_t*)(smem + boff);
                    b[nt][1] = *(const uint32_t*)(smem + boff + 16);
                }
#pragma unroll
                for (int mt = 0; mt < 2; mt++)
#pragma unroll
                    for (int nt = 0; nt < 4; nt++)
                        mma16816(d[mt][nt], a[mt], b[nt]);
            }
        }
        __syncthreads();

        // prefetch A tile i+2 into the buffer just freed
        if (i + 2 < NMT){
            const __nv_bfloat16* src = (var ? g_outl : g_outh)
                + (size_t)((mt0+i+2)*128 + row)*DD + half*32;
            uint32_t dst = sbm + SB_A + (i & 1)*2*HM_TILE + var*HM_TILE + row*HM_STRIDE + half*64;
#pragma unroll
            for (int j = 0; j < 4; j++) cpa16(dst + j*16, (const char*)src + j*16);
        }
        cpa_commit();

        // epilogue for tile i
        int m0 = (mt0 + i) * 128;
#pragma unroll
        for (int mt = 0; mt < 2; mt++){
            int r = m0 + mw*32 + mt*16 + g;
#pragma unroll
            for (int nt = 0; nt < 4; nt++){
                int col = n0 + nw*32 + nt*8 + tig*2;
                *(float2*)(out + (size_t)r*VV + col) =
                    make_float2(d[mt][nt][0] + bv[nt].x, d[mt][nt][1] + bv[nt].y);
                *(float2*)(out + (size_t)(r + 8)*VV + col) =
                    make_float2(d[mt][nt][2] + bv[nt].x, d[mt][nt][3] + bv[nt].y);
            }
        }
    }
}

// ---------------- launch ----------------
extern "C" void kernel_launch(void* const* d_in, const int* in_sizes, int n_in,
                              void* d_out, int out_size)
{
    const int*   x     = (const int*)  d_in[0];
    const float* tab   = (const float*)d_in[1];
    const float* Wm    = (const float*)d_in[2];
    const float* Um    = (const float*)d_in[3];
    const float* bm    = (const float*)d_in[4];
    const float* Wg    = (const float*)d_in[5];
    const float* bg    = (const float*)d_in[6];
    const float* W1    = (const float*)d_in[7];
    const float* b1    = (const float*)d_in[8];
    const float* W2    = (const float*)d_in[9];
    const float* b2    = (const float*)d_in[10];
    const float* ln_g  = (const float*)d_in[11];
    const float* ln_b  = (const float*)d_in[12];
    const float* headW = (const float*)d_in[13];
    const float* headb = (const float*)d_in[14];
    float* out = (float*)d_out;

    k_cvt_w<<<VV/128, 256>>>(headW);                            // head_W -> bf16 hi/lo (n-major)
    k_embA<<<BT, DD>>>(x, tab, Wm, bm);
    k_main<<<BB + BT/16, 256>>>(Um, W1, b1, W2, b2);           // recurrence || FFN
    k_combine<<<BT/256, 256>>>(Wg, bg, ln_g, ln_b);
    cudaFuncSetAttribute(k_head_mma, cudaFuncAttributeMaxDynamicSharedMemorySize, HM_TOTAL);
    k_head_mma<<<dim3(VV/128, BT/(128*NMT)), 512, HM_TOTAL>>>(headb, out);
}

// round 13
// speedup vs baseline: 1.4458x; 1.3300x over previous
#include <cuda_runtime.h>
#include <cuda_bf16.h>
#include <cstdint>
#include <stdint.h>
#include <math.h>

#define VV 16000
#define BB 8
#define TT 1024
#define DD 64
#define FF 256
#define EE 8
#define BT (BB*TT)

// ---------------- device scratch (no allocations allowed) ----------------
__device__ float g_emb[BT*DD];        // 2 MB   embedded tokens (fp32, residual path)
__device__ float g_A[BT*DD];          // 2 MB   x_t @ Wm + bm
__device__ float g_mem[BT*DD];        // 2 MB   recurrent state per step
__device__ float g_eo[BT*EE*DD];      // 16.8 MB per-expert FFN outputs (pre-gate)
__device__ __nv_bfloat16 g_embh[BT*DD];   // 1 MB  emb bf16 (FFN input)
__device__ __nv_bfloat16 g_outh[BT*DD];   // 1 MB  LN output, bf16 hi
__device__ __nv_bfloat16 g_outl[BT*DD];   // 1 MB  LN output, bf16 lo (residual)
__device__ __nv_bfloat16 g_hWh[VV*DD];    // 2 MB  head_W^T [n][k] bf16 hi
__device__ __nv_bfloat16 g_hWl[VV*DD];    // 2 MB  head_W^T [n][k] bf16 lo
__device__ __nv_bfloat16 g_W1t[EE*FF*DD]; // 256KB W1^T [e][f][k] bf16
__device__ __nv_bfloat16 g_W2t[EE*DD*FF]; // 256KB W2^T [e][d][f] bf16

typedef unsigned long long ull;

__device__ __forceinline__ float tanh_fast(float x){
    float r; asm("tanh.approx.f32 %0, %1;" : "=f"(r) : "f"(x)); return r;
}
__device__ __forceinline__ unsigned bf2(float lo, float hi){
    unsigned r; asm("cvt.rn.bf16x2.f32 %0, %1, %2;" : "=r"(r) : "f"(hi), "f"(lo)); return r;
}
__device__ __forceinline__ uint32_t smem_u32(const void* p){
    uint32_t a; asm("{ .reg .u64 t; cvta.to.shared.u64 t, %1; cvt.u32.u64 %0, t; }" : "=r"(a) : "l"(p));
    return a;
}
__device__ __forceinline__ void cpa16(uint32_t s, const void* g){
    asm volatile("cp.async.cg.shared.global [%0], [%1], 16;" :: "r"(s), "l"(g));
}
__device__ __forceinline__ void cpa_commit(){ asm volatile("cp.async.commit_group;"); }
__device__ __forceinline__ void cpa_wait1(){ asm volatile("cp.async.wait_group 1;"); }
__device__ __forceinline__ void cpa_wait0(){ asm volatile("cp.async.wait_group 0;"); }

__device__ __forceinline__ void ldm4(uint32_t a[4], uint32_t addr){
    asm volatile("ldmatrix.sync.aligned.m8n8.x4.shared.b16 {%0,%1,%2,%3}, [%4];"
                 : "=r"(a[0]), "=r"(a[1]), "=r"(a[2]), "=r"(a[3]) : "r"(addr));
}
__device__ __forceinline__ void mma16816(float d[4], const uint32_t a[4], const uint32_t b[2]){
    asm volatile("mma.sync.aligned.m16n8k16.row.col.f32.bf16.bf16.f32 "
                 "{%0,%1,%2,%3}, {%4,%5,%6,%7}, {%8,%9}, {%0,%1,%2,%3};"
                 : "+f"(d[0]), "+f"(d[1]), "+f"(d[2]), "+f"(d[3])
                 : "r"(a[0]), "r"(a[1]), "r"(a[2]), "r"(a[3]), "r"(b[0]), "r"(b[1]));
}

// ---------------- K0a: head_W -> transposed bf16 hi/lo ----------------
__global__ __launch_bounds__(256) void k_cvt_w(const float* __restrict__ hW)
{
    __shared__ float tile[64][132];
    int n0 = blockIdx.x * 128;
    int tid = threadIdx.x;
    for (int idx = tid; idx < 64*128; idx += 256){
        int k = idx >> 7, n = idx & 127;
        tile[k][n] = hW[(size_t)k*VV + n0 + n];
    }
    __syncthreads();
    int r = tid >> 1, k0 = (tid & 1) * 32;
    unsigned hw[16], lw[16];
#pragma unroll
    for (int q = 0; q < 16; q++){
        float a = tile[k0 + 2*q][r], b = tile[k0 + 2*q + 1][r];
        float ha = __bfloat162float(__float2bfloat16(a));
        float hb = __bfloat162float(__float2bfloat16(b));
        hw[q] = bf2(ha, hb);
        lw[q] = bf2(a - ha, b - hb);
    }
    uint4* dh = (uint4*)(g_hWh + (size_t)(n0 + r)*DD + k0);
    uint4* dl = (uint4*)(g_hWl + (size_t)(n0 + r)*DD + k0);
#pragma unroll
    for (int j = 0; j < 4; j++){ dh[j] = ((uint4*)hw)[j]; dl[j] = ((uint4*)lw)[j]; }
}

// ---------------- K0b: W1/W2 -> transposed bf16 ----------------
__global__ __launch_bounds__(256) void k_cvt_ffn(const float* __restrict__ W1,
                                                 const float* __restrict__ W2)
{
    __shared__ float t[8320];           // max(32*260, 64*68)
    int e = blockIdx.x;
    int tid = threadIdx.x;
    if (blockIdx.y == 0){
        // W1[e] [64 k][256 f] -> g_W1t[e][f][k]
        for (int c = 0; c < 2; c++){
            __syncthreads();
            for (int i = tid; i < 32*256; i += 256){
                int kk = i >> 8, f = i & 255;
                t[kk*260 + f] = W1[((size_t)e*64 + c*32 + kk)*256 + f];
            }
            __syncthreads();
            int f = tid;
            unsigned w[16];
#pragma unroll
            for (int q = 0; q < 16; q++)
                w[q] = bf2(t[(2*q)*260 + f], t[(2*q+1)*260 + f]);
            uint4* dst = (uint4*)(g_W1t + ((size_t)e*256 + f)*64 + c*32);
#pragma unroll
            for (int j = 0; j < 4; j++) dst[j] = ((uint4*)w)[j];
        }
    } else {
        // W2[e] [256 f][64 d] -> g_W2t[e][d][f]
        for (int c = 0; c < 4; c++){
            __syncthreads();
            for (int i = tid; i < 64*64; i += 256){
                int ff = i >> 6, d = i & 63;
                t[ff*68 + d] = W2[((size_t)e*256 + c*64 + ff)*64 + d];
            }
            __syncthreads();
            int d = tid >> 2, sub = tid & 3;
            unsigned w[8];
#pragma unroll
            for (int q = 0; q < 8; q++)
                w[q] = bf2(t[(sub*16 + 2*q)*68 + d], t[(sub*16 + 2*q + 1)*68 + d]);
            uint4* dst = (uint4*)(g_W2t + ((size_t)e*64 + d)*256 + c*64 + sub*16);
#pragma unroll
            for (int j = 0; j < 2; j++) dst[j] = ((uint4*)w)[j];
        }
    }
}

// ---------------- K1: embedding gather + A = emb @ Wm + bm ----------------
__global__ void k_embA(const int* __restrict__ x, const float* __restrict__ tab,
                       const float* __restrict__ Wm, const float* __restrict__ bm)
{
    int bt = blockIdx.x;
    int d  = threadIdx.x;
    __shared__ __align__(16) float xs[DD];
    float v = tab[x[bt]*DD + d];
    xs[d] = v;
    g_emb[bt*DD + d] = v;
    g_embh[bt*DD + d] = __float2bfloat16(v);
    __syncthreads();
    float acc = bm[d];
    const float4* xr = (const float4*)xs;
#pragma unroll
    for (int k4 = 0; k4 < 16; k4++){
        float4 m4 = xr[k4];
        acc += m4.x*Wm[(k4*4+0)*DD+d] + m4.y*Wm[(k4*4+1)*DD+d]
             + m4.z*Wm[(k4*4+2)*DD+d] + m4.w*Wm[(k4*4+3)*DD+d];
    }
    g_A[bt*DD + d] = acc;
}

// ---------------- K2: recurrence (blocks 0..7) || HMMA FFN (blocks 8..) ----------------
// FFN smem layout (dynamic):
#define FSX   0                        // X  [64 m][72 bf16]  (144 B rows)
#define FSW1  9216                     // W1t [256 f][72 bf16]
#define FSH   46080                    // H  [64 m][264 bf16] (528 B rows)
#define FSW2  79872                    // W2t [64 d][264 bf16]
#define FTOT  113664

__global__ __launch_bounds__(256) void k_main(
    const float* __restrict__ Um,
    const float* __restrict__ b1, const float* __restrict__ b2)
{
    extern __shared__ char smem[];
    if (blockIdx.x < BB) {
        float* sm_mem = (float*)smem;          // 64
        float* sp     = sm_mem + 64;           // 4*64
        int b   = blockIdx.x;
        int tid = threadIdx.x;
        int d = tid & 63, q = tid >> 6;
        float um[16];
#pragma unroll
        for (int j = 0; j < 16; j++) um[j] = Um[(q*16 + j)*DD + d];
        if (q == 0) sm_mem[d] = 0.f;
        __syncthreads();
        const float* Ab = g_A  + b*TT*DD;
        float*       Mb = g_mem + b*TT*DD;
        float a_next = (q == 0) ? Ab[d] : 0.f;
        for (int t = 0; t < TT; t++){
            float a_pref = 0.f;
            if (q == 0 && t + 1 < TT) a_pref = Ab[(t+1)*DD + d];
            float p = 0.f;
            const float4* mv = (const float4*)(sm_mem + q*16);
#pragma unroll
            for (int j4 = 0; j4 < 4; j4++){
                float4 m4 = mv[j4];
                p += m4.x*um[j4*4+0] + m4.y*um[j4*4+1] + m4.z*um[j4*4+2] + m4.w*um[j4*4+3];
            }
            sp[q*64 + d] = p;
            __syncthreads();
            if (q == 0){
                float v = a_next + sp[d] + sp[64+d] + sp[128+d] + sp[192+d];
                float m = tanh_fast(v);
                sm_mem[d]   = m;
                Mb[t*DD + d] = m;
            }
            a_next = a_pref;
            __syncthreads();
        }
    } else {
        uint32_t sbm = smem_u32(smem);
        int idx = blockIdx.x - BB;
        int e = idx & 7, tok0 = (idx >> 3) * 64;
        int tid = threadIdx.x;
        int wid = tid >> 5, lane = tid & 31;

        // ---- async loads: X, W1t, W2t ----
        {
            int row = tid >> 2, q = tid & 3;   // X: 64 rows x 128B
            const char* src = (const char*)(g_embh + (size_t)(tok0 + row)*DD) + q*32;
            uint32_t dst = sbm + FSX + row*144 + q*32;
            cpa16(dst, src); cpa16(dst + 16, src + 16);
        }
        {
            int row = tid;                     // W1t: 256 rows x 128B
            const char* src = (const char*)(g_W1t + ((size_t)e*256 + row)*64);
            uint32_t dst = sbm + FSW1 + row*144;
#pragma unroll
            for (int j = 0; j < 8; j++) cpa16(dst + j*16, src + j*16);
        }
        {
            int row = tid >> 2, q = tid & 3;   // W2t: 64 rows x 512B
            const char* src = (const char*)(g_W2t + ((size_t)e*64 + row)*256) + q*128;
            uint32_t dst = sbm + FSW2 + row*528 + q*128;
#pragma unroll
            for (int j = 0; j < 8; j++) cpa16(dst + j*16, src + j*16);
        }
        cpa_commit();
        cpa_wait0();
        __syncthreads();

        int g = lane >> 2, tig = lane & 3;
        int lr = lane & 7, sel = lane >> 3;
        int aoffX = (lr + (sel & 1)*8)*144 + ((sel >> 1)*8)*2;
        int aoffH = (lr + (sel & 1)*8)*528 + ((sel >> 1)*8)*2;

        // ---- GEMM1: H = gelu(X @ W1t^T + b1) ; warp grid 4(M) x 2(N), tile 16x128 ----
        {
            int mw = wid & 3, nw = wid >> 2;
            float d1[16][4];
#pragma unroll
            for (int nt = 0; nt < 16; nt++)
#pragma unroll
                for (int q = 0; q < 4; q++) d1[nt][q] = 0.f;
#pragma unroll
            for (int kt = 0; kt < 4; kt++){
                uint32_t a[4];
                ldm4(a, sbm + FSX + (mw*16)*144 + kt*32 + aoffX);
#pragma unroll
                for (int nt = 0; nt < 16; nt++){
                    int brow = nw*128 + nt*8 + g;
                    uint32_t b[2];
                    b[0] = *(const uint32_t*)(smem + FSW1 + brow*144 + kt*32 + tig*4);
                    b[1] = *(const uint32_t*)(smem + FSW1 + brow*144 + kt*32 + tig*4 + 16);
                    mma16816(d1[nt], a, b);
                }
            }
            int r0 = mw*16 + g;
#pragma unroll
            for (int nt = 0; nt < 16; nt++){
                int col = nw*128 + nt*8 + tig*2;
                float bb0 = b1[e*FF + col], bb1 = b1[e*FF + col + 1];
                float a0 = d1[nt][0] + bb0, a1 = d1[nt][1] + bb1;
                float a2 = d1[nt][2] + bb0, a3 = d1[nt][3] + bb1;
                float v0 = 0.5f*a0*(1.f + erff(a0*0.70710678118654752440f));
                float v1 = 0.5f*a1*(1.f + erff(a1*0.70710678118654752440f));
                float v2 = 0.5f*a2*(1.f + erff(a2*0.70710678118654752440f));
                float v3 = 0.5f*a3*(1.f + erff(a3*0.70710678118654752440f));
                *(unsigned*)(smem + FSH + r0*528 + col*2)       = bf2(v0, v1);
                *(unsigned*)(smem + FSH + (r0+8)*528 + col*2)   = bf2(v2, v3);
            }
        }
        __syncthreads();

        // ---- GEMM2: eo = H @ W2t^T + b2 ; warp grid 2(M) x 4(N), tile 32x16 ----
        {
            int mw = wid & 1, nw = wid >> 1;
            float d2[2][2][4];
#pragma unroll
            for (int mt = 0; mt < 2; mt++)
#pragma unroll
                for (int nt = 0; nt < 2; nt++)
#pragma unroll
                    for (int q = 0; q < 4; q++) d2[mt][nt][q] = 0.f;
#pragma unroll
            for (int kt = 0; kt < 16; kt++){
                uint32_t a[2][4];
#pragma unroll
                for (int mt = 0; mt < 2; mt++)
                    ldm4(a[mt], sbm + FSH + (mw*32 + mt*16)*528 + kt*32 + aoffH);
#pragma unroll
                for (int nt = 0; nt < 2; nt++){
                    int brow = nw*16 + nt*8 + g;
                    uint32_t b[2];
                    b[0] = *(const uint32_t*)(smem + FSW2 + brow*528 + kt*32 + tig*4);
                    b[1] = *(const uint32_t*)(smem + FSW2 + brow*528 + kt*32 + tig*4 + 16);
#pragma unroll
                    for (int mt = 0; mt < 2; mt++)
                        mma16816(d2[mt][nt], a[mt], b);
                }
            }
#pragma unroll
            for (int mt = 0; mt < 2; mt++){
                int r = tok0 + mw*32 + mt*16 + g;
#pragma unroll
                for (int nt = 0; nt < 2; nt++){
                    int col = nw*16 + nt*8 + tig*2;
                    float bb0 = b2[e*DD + col], bb1 = b2[e*DD + col + 1];
                    *(float2*)(g_eo + ((size_t)r*EE + e)*DD + col) =
                        make_float2(d2[mt][nt][0] + bb0, d2[mt][nt][1] + bb1);
                    *(float2*)(g_eo + ((size_t)(r+8)*EE + e)*DD + col) =
                        make_float2(d2[mt][nt][2] + bb0, d2[mt][nt][3] + bb1);
                }
            }
        }
    }
}

// ---------------- K3: gates + gated sum + residual + LN -> bf16 hi/lo ----------------
// 8 lanes per token; 32 tokens per 256-thread block; grid 256.
__global__ __launch_bounds__(256) void k_combine(
    const float* __restrict__ Wg, const float* __restrict__ bg,
    const float* __restrict__ ln_g, const float* __restrict__ ln_b)
{
    __shared__ float sWg[DD*EE];
    __shared__ float sg[DD], sb[DD], sbg[EE];
    int tid = threadIdx.x;
    for (int i = tid; i < DD*EE; i += 256) sWg[i] = Wg[i];
    if (tid < DD){ sg[tid] = ln_g[tid]; sb[tid] = ln_b[tid]; }
    if (tid < EE) sbg[tid] = bg[tid];
    __syncthreads();

    int j  = tid & 7;                       // lane-in-token = expert id / d-octet
    int bt = blockIdx.x*32 + (tid >> 3);

    // gate logit for expert j
    float gl = sbg[j];
    const float4* mr = (const float4*)(g_mem + (size_t)bt*DD);
#pragma unroll
    for (int k4 = 0; k4 < 16; k4++){
        float4 m4 = mr[k4];
        gl += m4.x*sWg[(k4*4+0)*EE+j] + m4.y*sWg[(k4*4+1)*EE+j]
            + m4.z*sWg[(k4*4+2)*EE+j] + m4.w*sWg[(k4*4+3)*EE+j];
    }
    // softmax over the 8-lane group
    float mx = gl;
#pragma unroll
    for (int s = 1; s < 8; s <<= 1) mx = fmaxf(mx, __shfl_xor_sync(0xffffffffu, mx, s, 8));
    float ge = expf(gl - mx);
    float sum = ge;
#pragma unroll
    for (int s = 1; s < 8; s <<= 1) sum += __shfl_xor_sync(0xffffffffu, sum, s, 8);
    ge /= sum;

    // lane j owns d in [8j, 8j+8)
    float acc[8];
    {
        const float4* er = (const float4*)(g_emb + (size_t)bt*DD + 8*j);
        float4 v0 = er[0], v1 = er[1];
        acc[0]=v0.x; acc[1]=v0.y; acc[2]=v0.z; acc[3]=v0.w;
        acc[4]=v1.x; acc[5]=v1.y; acc[6]=v1.z; acc[7]=v1.w;
    }
#pragma unroll
    for (int e = 0; e < EE; e++){
        float w = __shfl_sync(0xffffffffu, ge, e, 8);
        const float4* eor = (const float4*)(g_eo + ((size_t)bt*EE + e)*DD + 8*j);
        float4 v0 = eor[0], v1 = eor[1];
        acc[0]+=w*v0.x; acc[1]+=w*v0.y; acc[2]+=w*v0.z; acc[3]+=w*v0.w;
        acc[4]+=w*v1.x; acc[5]+=w*v1.y; acc[6]+=w*v1.z; acc[7]+=w*v1.w;
    }
    float s1 = 0.f, s2 = 0.f;
#pragma unroll
    for (int i = 0; i < 8; i++){ s1 += acc[i]; s2 += acc[i]*acc[i]; }
#pragma unroll
    for (int s = 1; s < 8; s <<= 1){
        s1 += __shfl_xor_sync(0xffffffffu, s1, s, 8);
        s2 += __shfl_xor_sync(0xffffffffu, s2, s, 8);
    }
    float mu = s1 * (1.f/DD);
    float var = s2 * (1.f/DD) - mu*mu;
    float rs = rsqrtf(var + 1e-5f);

    unsigned hw[4], lw[4];
#pragma unroll
    for (int i = 0; i < 4; i++){
        float o0 = sg[8*j+2*i+0]*(acc[2*i+0]-mu)*rs + sb[8*j+2*i+0];
        float o1 = sg[8*j+2*i+1]*(acc[2*i+1]-mu)*rs + sb[8*j+2*i+1];
        float h0 = __bfloat162float(__float2bfloat16(o0));
        float h1 = __bfloat162float(__float2bfloat16(o1));
        hw[i] = bf2(h0, h1);
        lw[i] = bf2(o0 - h0, o1 - h1);
    }
    *(uint4*)(g_outh + (size_t)bt*DD + 8*j) = *(uint4*)hw;
    *(uint4*)(g_outl + (size_t)bt*DD + 8*j) = *(uint4*)lw;
}

// ---------------- K4: head GEMM, B-resident, 16 warps/CTA (HMMA bf16x3) ----------------
#define HM_STRIDE 144
#define HM_TILE   (128*HM_STRIDE)
#define SB_BHI    0
#define SB_BLO    HM_TILE
#define SB_A      (2*HM_TILE)
#define HM_TOTAL  (SB_A + 2*2*HM_TILE)
#define NMT 8

__global__ __launch_bounds__(512) void k_head_mma(
    const float* __restrict__ hb, float* __restrict__ out)
{
    extern __shared__ char smem[];
    uint32_t sbm = smem_u32(smem);
    int tid = threadIdx.x;
    int wid = tid >> 5, lane = tid & 31;
    int n0 = blockIdx.x * 128;
    int mt0 = blockIdx.y * NMT;

    int var  = (tid >> 7) & 1;
    int row  = tid & 127;
    int half = tid >> 8;

    {
        const __nv_bfloat16* src = (var ? g_hWl : g_hWh) + (size_t)(n0 + row)*DD + half*32;
        uint32_t dst = sbm + (var ? SB_BLO : SB_BHI) + row*HM_STRIDE + half*64;
#pragma unroll
        for (int j = 0; j < 4; j++) cpa16(dst + j*16, (const char*)src + j*16);
    }
    {
        const __nv_bfloat16* src = (var ? g_outl : g_outh) + (size_t)(mt0*128 + row)*DD + half*32;
        uint32_t dst = sbm + SB_A + var*HM_TILE + row*HM_STRIDE + half*64;
#pragma unroll
        for (int j = 0; j < 4; j++) cpa16(dst + j*16, (const char*)src + j*16);
    }
    cpa_commit();
    {
        const __nv_bfloat16* src = (var ? g_outl : g_outh) + (size_t)((mt0+1)*128 + row)*DD + half*32;
        uint32_t dst = sbm + SB_A + 2*HM_TILE + var*HM_TILE + row*HM_STRIDE + half*64;
#pragma unroll
        for (int j = 0; j < 4; j++) cpa16(dst + j*16, (const char*)src + j*16);
    }
    cpa_commit();

    int mw = wid & 3, nw = wid >> 2;
    int g = lane >> 2, tig = lane & 3;
    int lr = lane & 7, sel = lane >> 3;
    int a_lane_off = (lr + (sel & 1)*8)*HM_STRIDE + ((sel >> 1)*8)*2;

    float2 bv[4];
#pragma unroll
    for (int nt = 0; nt < 4; nt++)
        bv[nt] = *(const float2*)(hb + n0 + nw*32 + nt*8 + tig*2);

    for (int i = 0; i < NMT; i++){
        cpa_wait1();
        __syncthreads();

        float d[2][4][4];
#pragma unroll
        for (int mt = 0; mt < 2; mt++)
#pragma unroll
            for (int nt = 0; nt < 4; nt++)
#pragma unroll
                for (int q = 0; q < 4; q++) d[mt][nt][q] = 0.f;

        uint32_t abase = sbm + SB_A + (i & 1)*2*HM_TILE;
#pragma unroll
        for (int pass = 0; pass < 3; pass++){
            uint32_t Ab = abase + ((pass == 2) ? HM_TILE : 0);
            uint32_t Boff = (pass == 1) ? SB_BLO : SB_BHI;
#pragma unroll
            for (int kt = 0; kt < 4; kt++){
                int k0 = kt*16;
                uint32_t a[2][4];
#pragma unroll
                for (int mt = 0; mt < 2; mt++)
                    ldm4(a[mt], Ab + (mw*32 + mt*16)*HM_STRIDE + k0*2 + a_lane_off);
                uint32_t b[4][2];
#pragma unroll
                for (int nt = 0; nt < 4; nt++){
                    int boff = Boff + (nw*32 + nt*8 + g)*HM_STRIDE + (k0 + tig*2)*2;
                    b[nt][0] = *(const uint32_t*)(smem + boff);
                    b[nt][1] = *(const uint32_t*)(smem + boff + 16);
                }
#pragma unroll
                for (int mt = 0; mt < 2; mt++)
#pragma unroll
                    for (int nt = 0; nt < 4; nt++)
                        mma16816(d[mt][nt], a[mt], b[nt]);
            }
        }
        __syncthreads();

        if (i + 2 < NMT){
            const __nv_bfloat16* src = (var ? g_outl : g_outh)
                + (size_t)((mt0+i+2)*128 + row)*DD + half*32;
            uint32_t dst = sbm + SB_A + (i & 1)*2*HM_TILE + var*HM_TILE + row*HM_STRIDE + half*64;
#pragma unroll
            for (int j = 0; j < 4; j++) cpa16(dst + j*16, (const char*)src + j*16);
        }
        cpa_commit();

        int m0 = (mt0 + i) * 128;
#pragma unroll
        for (int mt = 0; mt < 2; mt++){
            int r = m0 + mw*32 + mt*16 + g;
#pragma unroll
            for (int nt = 0; nt < 4; nt++){
                int col = n0 + nw*32 + nt*8 + tig*2;
                *(float2*)(out + (size_t)r*VV + col) =
                    make_float2(d[mt][nt][0] + bv[nt].x, d[mt][nt][1] + bv[nt].y);
                *(float2*)(out + (size_t)(r + 8)*VV + col) =
                    make_float2(d[mt][nt][2] + bv[nt].x, d[mt][nt][3] + bv[nt].y);
            }
        }
    }
}

// ---------------- launch ----------------
extern "C" void kernel_launch(void* const* d_in, const int* in_sizes, int n_in,
                              void* d_out, int out_size)
{
    const int*   x     = (const int*)  d_in[0];
    const float* tab   = (const float*)d_in[1];
    const float* Wm    = (const float*)d_in[2];
    const float* Um    = (const float*)d_in[3];
    const float* bm    = (const float*)d_in[4];
    const float* Wg    = (const float*)d_in[5];
    const float* bg    = (const float*)d_in[6];
    const float* W1    = (const float*)d_in[7];
    const float* b1    = (const float*)d_in[8];
    const float* W2    = (const float*)d_in[9];
    const float* b2    = (const float*)d_in[10];
    const float* ln_g  = (const float*)d_in[11];
    const float* ln_b  = (const float*)d_in[12];
    const float* headW = (const float*)d_in[13];
    const float* headb = (const float*)d_in[14];
    float* out = (float*)d_out;

    k_cvt_w<<<VV/128, 256>>>(headW);
    k_cvt_ffn<<<dim3(EE, 2), 256>>>(W1, W2);
    k_embA<<<BT, DD>>>(x, tab, Wm, bm);
    cudaFuncSetAttribute(k_main, cudaFuncAttributeMaxDynamicSharedMemorySize, FTOT);
    k_main<<<BB + (BT/64)*EE, 256, FTOT>>>(Um, b1, b2);        // recurrence || HMMA FFN
    k_combine<<<BT/32, 256>>>(Wg, bg, ln_g, ln_b);
    cudaFuncSetAttribute(k_head_mma, cudaFuncAttributeMaxDynamicSharedMemorySize, HM_TOTAL);
    k_head_mma<<<dim3(VV/128, BT/(128*NMT)), 512, HM_TOTAL>>>(headb, out);
}